// round 12
// baseline (speedup 1.0000x reference)
#include <cuda_runtime.h>
#include <cuda_bf16.h>
#include <cstdint>
#include <math.h>

#define S_LEN 2048
#define DM    1024
#define NH    16
#define DH    64
#define BATCH 2
#define MROWS (BATCH * S_LEN)   // 4096
#define QKV_STRIDE ((size_t)MROWS * DM)

using bf16 = __nv_bfloat16;

// ================= helpers =================
__device__ __forceinline__ uint32_t smem_to_u32(const void* p) {
    uint32_t a;
    asm("{ .reg .u64 t; cvta.to.shared.u64 t, %1; cvt.u32.u64 %0, t; }" : "=r"(a) : "l"(p));
    return a;
}
__device__ __forceinline__ void cp_async16(uint32_t saddr, const void* gaddr) {
    asm volatile("cp.async.cg.shared.global [%0], [%1], 16;" :: "r"(saddr), "l"(gaddr));
}
__device__ __forceinline__ void ldsm_x4(uint32_t* r, uint32_t addr) {
    asm volatile("ldmatrix.sync.aligned.m8n8.x4.shared.b16 {%0,%1,%2,%3}, [%4];"
                 : "=r"(r[0]), "=r"(r[1]), "=r"(r[2]), "=r"(r[3]) : "r"(addr));
}
__device__ __forceinline__ void ldsm_x2(uint32_t* r, uint32_t addr) {
    asm volatile("ldmatrix.sync.aligned.m8n8.x2.shared.b16 {%0,%1}, [%2];"
                 : "=r"(r[0]), "=r"(r[1]) : "r"(addr));
}
__device__ __forceinline__ void ldsm_x2t(uint32_t* r, uint32_t addr) {
    asm volatile("ldmatrix.sync.aligned.m8n8.x2.trans.shared.b16 {%0,%1}, [%2];"
                 : "=r"(r[0]), "=r"(r[1]) : "r"(addr));
}
// D += A(16x16 bf16, row) * B(16x8 bf16, col), fp32 acc
__device__ __forceinline__ void mma16816(float* d, const uint32_t* a, const uint32_t* b) {
    asm volatile(
        "mma.sync.aligned.m16n8k16.row.col.f32.bf16.bf16.f32 "
        "{%0,%1,%2,%3}, {%4,%5,%6,%7}, {%8,%9}, {%0,%1,%2,%3};\n"
        : "+f"(d[0]), "+f"(d[1]), "+f"(d[2]), "+f"(d[3])
        : "r"(a[0]), "r"(a[1]), "r"(a[2]), "r"(a[3]), "r"(b[0]), "r"(b[1]));
}
// pack two fp32 into bf16x2 (hi part) plus residual bf16x2 (lo part)
__device__ __forceinline__ void pack_pair(float p0, float p1, uint32_t& hi, uint32_t& lo) {
    __nv_bfloat162 h = __floats2bfloat162_rn(p0, p1);   // .x = p0 (low half)
    hi = *(uint32_t*)&h;
    const float l0 = p0 - __bfloat162float(h.x);
    const float l1 = p1 - __bfloat162float(h.y);
    __nv_bfloat162 l = __floats2bfloat162_rn(l0, l1);
    lo = *(uint32_t*)&l;
}

// ---- scratch (device globals) ----
__device__ bf16 g_QKVhi[3][BATCH * NH * S_LEN * DH];   // [B,H,S,Dh] x {Q,K,V}
__device__ bf16 g_QKVlo[3][BATCH * NH * S_LEN * DH];
__device__ bf16 g_xhi[MROWS * DM];
__device__ bf16 g_xlo[MROWS * DM];
__device__ bf16 g_ahi[MROWS * DM];
__device__ bf16 g_alo[MROWS * DM];
__device__ bf16 g_wThi[4][DM * DM];   // q,k,v,o  ([N,K] layout)
__device__ bf16 g_wTlo[4][DM * DM];
__device__ float g_proj[MROWS * DM];

// ============================================================
// fp32 -> bf16 hi/lo split (same layout)
// ============================================================
__global__ __launch_bounds__(256)
void cvt_hilo(const float* __restrict__ in, bf16* __restrict__ hi,
              bf16* __restrict__ lo) {
    const int i = blockIdx.x * 256 + threadIdx.x;
    const float v = in[i];
    const bf16 h = __float2bfloat16(v);
    hi[i] = h;
    lo[i] = __float2bfloat16(v - __bfloat162float(h));
}

// all 4 weights [K=1024, N=1024] fp32 -> wT hi/lo [N, K] bf16, smem transpose
__global__ __launch_bounds__(256)
void cvt_wT_all(const float* __restrict__ w0, const float* __restrict__ w1,
                const float* __restrict__ w2, const float* __restrict__ w3,
                bf16* __restrict__ hiT, bf16* __restrict__ loT) {
    __shared__ float t[32][33];
    const float* ws[4] = { w0, w1, w2, w3 };
    const int z = blockIdx.z;
    const float* w = ws[z];
    const int bn = blockIdx.x * 32, bk = blockIdx.y * 32;
    const int tx = threadIdx.x, ty = threadIdx.y;   // block (32, 8)
#pragma unroll
    for (int i = 0; i < 32; i += 8)
        t[ty + i][tx] = w[(size_t)(bk + ty + i) * DM + bn + tx];
    __syncthreads();
    const size_t zoff = (size_t)z * DM * DM;
#pragma unroll
    for (int i = 0; i < 32; i += 8) {
        const float v = t[tx][ty + i];                 // = w[bk+tx][bn+ty+i]
        const bf16 h = __float2bfloat16(v);
        const size_t o = zoff + (size_t)(bn + ty + i) * DM + bk + tx;
        hiT[o] = h;
        loT[o] = __float2bfloat16(v - __bfloat162float(h));
    }
}

// ============================================================
// HMMA split-bf16 GEMM: C[4096,1024] = A @ B^T (B stored [N,K]).
// D = Ahi*Bhi + Ahi*Blo + Alo*Bhi, fp32 accumulate.
// 128x128 block tile, K-tile 32, 8 warps (4x2), warp 32x64.
// cp.async double buffer. smem row stride 40 bf16 (80B).
// blockIdx.z selects weight slot (and output slot in MODE 1).
// MODE 0: fp32 C row-major.  MODE 1: bf16 hi/lo scatter to [B,H,S,Dh].
// __launch_bounds__(256,2): 2 CTAs/SM.
// ============================================================
template <int MODE>
__global__ __launch_bounds__(256, 2)
void mma_gemm(const bf16* __restrict__ Ahi, const bf16* __restrict__ Alo,
              const bf16* __restrict__ BhiB, const bf16* __restrict__ BloB,
              float* __restrict__ C, bf16* __restrict__ ChiB, bf16* __restrict__ CloB)
{
    extern __shared__ char smd[];
    const int tid = threadIdx.x;
    const int lane = tid & 31, wid = tid >> 5;
    const int wm = wid & 3, wn = wid >> 2;            // 4 x 2 warp grid
    const int m0 = blockIdx.y * 128, n0 = blockIdx.x * 128;
    const int z = blockIdx.z;
    const uint32_t sb = smem_to_u32(smd);

    const bf16* Bhi = BhiB + (size_t)z * DM * DM;
    const bf16* Blo = BloB + (size_t)z * DM * DM;
    const bf16* srcs[4] = { Ahi + (size_t)m0 * DM, Alo + (size_t)m0 * DM,
                            Bhi + (size_t)n0 * DM, Blo + (size_t)n0 * DM };

    auto prefetch = [&](int kt) {
        const uint32_t bb = sb + (kt & 1) * 40960;
        const int k0 = kt * 32;
#pragma unroll
        for (int t = 0; t < 4; t++) {
            const bf16* s = srcs[t] + k0;
            const uint32_t tb = bb + t * 10240;
#pragma unroll
            for (int i = 0; i < 2; i++) {
                const int idx = i * 256 + tid;
                const int r = idx >> 2, c = idx & 3;
                cp_async16(tb + r * 80 + c * 16, s + (size_t)r * DM + c * 8);
            }
        }
        asm volatile("cp.async.commit_group;");
    };

    prefetch(0);
    prefetch(1);

    float acc[2][8][4];
#pragma unroll
    for (int mt = 0; mt < 2; mt++)
#pragma unroll
        for (int nt = 0; nt < 8; nt++)
#pragma unroll
            for (int e = 0; e < 4; e++) acc[mt][nt][e] = 0.f;

    const int KT = DM / 32;   // 32
    for (int kt = 0; kt < KT; kt++) {
        if (kt == KT - 1) asm volatile("cp.async.wait_group 0;" ::: "memory");
        else              asm volatile("cp.async.wait_group 1;" ::: "memory");
        __syncthreads();
        const uint32_t bb = sb + (kt & 1) * 40960;
#pragma unroll
        for (int ks = 0; ks < 2; ks++) {
            const int kk = ks * 16;
            uint32_t ah[2][4], al[2][4];
            const uint32_t acol = (uint32_t)(kk + (lane >> 4) * 8) * 2;
#pragma unroll
            for (int mt = 0; mt < 2; mt++) {
                const uint32_t ra = bb + (uint32_t)(wm * 32 + mt * 16 + (lane & 15)) * 80 + acol;
                ldsm_x4(ah[mt], ra);
                ldsm_x4(al[mt], ra + 10240);
            }
#pragma unroll
            for (int nt = 0; nt < 8; nt++) {
                uint32_t bhf[2], blf[2];
                const uint32_t rb = bb + 20480
                    + (uint32_t)(wn * 64 + nt * 8 + (lane & 7)) * 80
                    + (uint32_t)(kk + ((lane >> 3) & 1) * 8) * 2;
                ldsm_x2(bhf, rb);
                ldsm_x2(blf, rb + 10240);
#pragma unroll
                for (int mt = 0; mt < 2; mt++) {
                    mma16816(acc[mt][nt], ah[mt], bhf);
                    mma16816(acc[mt][nt], ah[mt], blf);
                    mma16816(acc[mt][nt], al[mt], bhf);
                }
            }
        }
        __syncthreads();
        if (kt + 2 < KT) prefetch(kt + 2);
    }

    bf16* Chi = (MODE == 1) ? ChiB + (size_t)z * QKV_STRIDE : nullptr;
    bf16* Clo = (MODE == 1) ? CloB + (size_t)z * QKV_STRIDE : nullptr;

#pragma unroll
    for (int mt = 0; mt < 2; mt++)
#pragma unroll
    for (int nt = 0; nt < 8; nt++) {
        const int r0 = m0 + wm * 32 + mt * 16 + (lane >> 2);
        const int c0 = n0 + wn * 64 + nt * 8 + (lane & 3) * 2;
#pragma unroll
        for (int e = 0; e < 4; e++) {
            const int r = r0 + (e >> 1) * 8;
            const int c = c0 + (e & 1);
            const float v = acc[mt][nt][e];
            if (MODE == 0) {
                C[(size_t)r * DM + c] = v;
            } else {
                const int b = r >> 11, s = r & 2047;
                const int h = c >> 6, d = c & 63;
                const size_t o = (((size_t)(b * NH + h)) * S_LEN + s) * DH + d;
                const bf16 hv = __float2bfloat16(v);
                Chi[o] = hv;
                Clo[o] = __float2bfloat16(v - __bfloat162float(hv));
            }
        }
    }
}

// ============================================================
// FA2-style HMMA flash attention: BM=128, BN=64, Dh=64, 8 warps.
// Each warp: 16 query rows x full 64 kv cols x full 64 d.
// S acc in registers; softmax via quad shfl; P repacked from
// C-frag into A-frag in registers. 3-pass hi/lo split.
// __launch_bounds__(256,2) -> 2 CTAs/SM; Q-lo frags reloaded per
// kv-tile (not hoisted) to fit the 128-reg budget.
// ============================================================
__global__ __launch_bounds__(256, 2)
void attn_kernel() {
    extern __shared__ char smd[];
    const int tid = threadIdx.x, lane = tid & 31, wid = tid >> 5;
    const int qt = (int)gridDim.x - 1 - (int)blockIdx.x;   // heavy tiles first
    const int bh = blockIdx.y;
    const int b = bh >> 4, h = bh & 15;
    const int q0 = qt * 128;
    const int groupID = lane >> 2, tid4 = lane & 3;
    const uint32_t sb = smem_to_u32(smd);
    const uint32_t QHo = 0;                        // Qhi 128x144B, Qlo at +18432
    const uint32_t KV0 = 36864, KVSZ = 36864;      // per buf: Khi,Klo,Vhi,Vlo (64x144B each)
    const int nkt = 2 * qt + 2;

    const size_t base_off = (size_t)bh * S_LEN * DH;

    // Q hi/lo loads (group 0, together with KV tile 0)
    {
        const bf16* qh = g_QKVhi[0] + base_off + (size_t)q0 * DH;
        const bf16* ql = g_QKVlo[0] + base_off + (size_t)q0 * DH;
#pragma unroll
        for (int i = 0; i < 4; i++) {
            const int idx = i * 256 + tid;
            const int r = idx >> 3, c = idx & 7;
            cp_async16(sb + QHo + r * 144 + c * 16, qh + r * 64 + c * 8);
            cp_async16(sb + QHo + 18432 + r * 144 + c * 16, ql + r * 64 + c * 8);
        }
    }
    auto kvload = [&](int kt) {
        const uint32_t bb = sb + KV0 + (kt & 1) * KVSZ;
        const size_t off = base_off + (size_t)kt * 64 * DH;
        const bf16* srcs[4] = { g_QKVhi[1] + off, g_QKVlo[1] + off,
                                g_QKVhi[2] + off, g_QKVlo[2] + off };
#pragma unroll
        for (int t = 0; t < 4; t++) {
            const uint32_t tb = bb + t * 9216;
            const bf16* s = srcs[t];
#pragma unroll
            for (int i = 0; i < 2; i++) {
                const int idx = i * 256 + tid;
                const int r = idx >> 3, c = idx & 7;
                cp_async16(tb + r * 144 + c * 16, s + r * 64 + c * 8);
            }
        }
        asm volatile("cp.async.commit_group;");
    };
    kvload(0);           // G0 = Q + KV0
    kvload(1);           // G1 = KV1   (nkt >= 2 always)
    asm volatile("cp.async.wait_group 1;" ::: "memory");
    __syncthreads();

    // Hoist only Q-hi fragments (Q-lo reloaded per kv-tile to save regs)
    const uint32_t qrow_addr = sb + QHo + (uint32_t)(wid * 16 + (lane & 15)) * 144
                               + (uint32_t)((lane >> 4) * 8) * 2;
    uint32_t qhf[4][4];
#pragma unroll
    for (int ks = 0; ks < 4; ks++) ldsm_x4(qhf[ks], qrow_addr + ks * 32);

    float rm0 = -1e30f, rm1 = -1e30f, rl0 = 0.f, rl1 = 0.f;
    float oacc[8][4];
#pragma unroll
    for (int nt = 0; nt < 8; nt++)
#pragma unroll
        for (int e = 0; e < 4; e++) oacc[nt][e] = 0.f;

    for (int kt = 0; kt < nkt; kt++) {
        const uint32_t kb = sb + KV0 + (kt & 1) * KVSZ;
        const uint32_t vb = kb + 18432;

        // ---- S = Q @ K^T (3-pass split), 16x64 per warp ----
        float sacc[8][4];
#pragma unroll
        for (int nt = 0; nt < 8; nt++)
#pragma unroll
            for (int e = 0; e < 4; e++) sacc[nt][e] = 0.f;

#pragma unroll
        for (int ks = 0; ks < 4; ks++) {
            uint32_t qlf[4];
            ldsm_x4(qlf, qrow_addr + 18432 + ks * 32);
#pragma unroll
            for (int nt = 0; nt < 8; nt++) {
                uint32_t khf[2], klf[2];
                const uint32_t rb = kb + (uint32_t)(nt * 8 + (lane & 7)) * 144
                                    + (uint32_t)(ks * 16 + ((lane >> 3) & 1) * 8) * 2;
                ldsm_x2(khf, rb);
                ldsm_x2(klf, rb + 9216);
                mma16816(sacc[nt], qhf[ks], khf);
                mma16816(sacc[nt], qhf[ks], klf);
                mma16816(sacc[nt], qlf, khf);
            }
        }

        // ---- scale + causal mask (in registers) ----
        const int row0 = q0 + wid * 16 + groupID;
#pragma unroll
        for (int nt = 0; nt < 8; nt++) {
            const int c0 = kt * 64 + nt * 8 + tid4 * 2;
#pragma unroll
            for (int e = 0; e < 4; e++) {
                const int col = c0 + (e & 1);
                const int row = row0 + ((e >> 1) << 3);
                const float v = sacc[nt][e] * 0.125f;
                sacc[nt][e] = (col > row) ? -10000000.0f : v;
            }
        }

        // ---- online softmax (quad shfl, rows groupID and groupID+8) ----
        float mx0 = rm0, mx1 = rm1;
#pragma unroll
        for (int nt = 0; nt < 8; nt++) {
            mx0 = fmaxf(mx0, fmaxf(sacc[nt][0], sacc[nt][1]));
            mx1 = fmaxf(mx1, fmaxf(sacc[nt][2], sacc[nt][3]));
        }
        mx0 = fmaxf(mx0, __shfl_xor_sync(0xffffffffu, mx0, 1));
        mx0 = fmaxf(mx0, __shfl_xor_sync(0xffffffffu, mx0, 2));
        mx1 = fmaxf(mx1, __shfl_xor_sync(0xffffffffu, mx1, 1));
        mx1 = fmaxf(mx1, __shfl_xor_sync(0xffffffffu, mx1, 2));
        float s0 = 0.f, s1 = 0.f;
#pragma unroll
        for (int nt = 0; nt < 8; nt++) {
            sacc[nt][0] = __expf(sacc[nt][0] - mx0); s0 += sacc[nt][0];
            sacc[nt][1] = __expf(sacc[nt][1] - mx0); s0 += sacc[nt][1];
            sacc[nt][2] = __expf(sacc[nt][2] - mx1); s1 += sacc[nt][2];
            sacc[nt][3] = __expf(sacc[nt][3] - mx1); s1 += sacc[nt][3];
        }
        s0 += __shfl_xor_sync(0xffffffffu, s0, 1);
        s0 += __shfl_xor_sync(0xffffffffu, s0, 2);
        s1 += __shfl_xor_sync(0xffffffffu, s1, 1);
        s1 += __shfl_xor_sync(0xffffffffu, s1, 2);
        const float sc0 = __expf(rm0 - mx0), sc1 = __expf(rm1 - mx1);
        rl0 = rl0 * sc0 + s0;  rl1 = rl1 * sc1 + s1;
        rm0 = mx0;  rm1 = mx1;
#pragma unroll
        for (int nt = 0; nt < 8; nt++) {
            oacc[nt][0] *= sc0; oacc[nt][1] *= sc0;
            oacc[nt][2] *= sc1; oacc[nt][3] *= sc1;
        }

        // ---- O += P @ V: repack C-frag -> A-frag in registers ----
#pragma unroll
        for (int j = 0; j < 4; j++) {
            uint32_t ph[4], pl[4];
            pack_pair(sacc[2 * j][0],     sacc[2 * j][1],     ph[0], pl[0]);
            pack_pair(sacc[2 * j][2],     sacc[2 * j][3],     ph[1], pl[1]);
            pack_pair(sacc[2 * j + 1][0], sacc[2 * j + 1][1], ph[2], pl[2]);
            pack_pair(sacc[2 * j + 1][2], sacc[2 * j + 1][3], ph[3], pl[3]);
#pragma unroll
            for (int nt = 0; nt < 8; nt++) {
                uint32_t vhf[2], vlf[2];
                const uint32_t rb = vb + (uint32_t)(j * 16 + (lane & 15)) * 144
                                    + (uint32_t)(nt * 8) * 2;
                ldsm_x2t(vhf, rb);
                ldsm_x2t(vlf, rb + 9216);
                mma16816(oacc[nt], ph, vhf);
                mma16816(oacc[nt], ph, vlf);
                mma16816(oacc[nt], pl, vhf);
            }
        }

        // ---- pipeline next KV tile ----
        if (kt + 1 < nkt) {
            __syncthreads();   // all warps done reading buf (kt&1)
            if (kt + 2 < nkt) {
                kvload(kt + 2);
                asm volatile("cp.async.wait_group 1;" ::: "memory");
            } else {
                asm volatile("cp.async.wait_group 0;" ::: "memory");
            }
        }
    }

    // ---- epilogue: O / l  -> bf16 hi/lo merged-head layout ----
    const float inv0 = 1.f / rl0, inv1 = 1.f / rl1;
    const size_t m0 = (size_t)b * S_LEN + q0 + wid * 16 + groupID;
    const size_t m1 = m0 + 8;
#pragma unroll
    for (int nt = 0; nt < 8; nt++) {
        const int n = h * 64 + nt * 8 + tid4 * 2;
        {
            const float v0 = oacc[nt][0] * inv0, v1 = oacc[nt][1] * inv0;
            __nv_bfloat162 hv = __floats2bfloat162_rn(v0, v1);
            const float l0 = v0 - __bfloat162float(hv.x);
            const float l1 = v1 - __bfloat162float(hv.y);
            *(__nv_bfloat162*)&g_ahi[m0 * DM + n] = hv;
            *(__nv_bfloat162*)&g_alo[m0 * DM + n] = __floats2bfloat162_rn(l0, l1);
        }
        {
            const float v0 = oacc[nt][2] * inv1, v1 = oacc[nt][3] * inv1;
            __nv_bfloat162 hv = __floats2bfloat162_rn(v0, v1);
            const float l0 = v0 - __bfloat162float(hv.x);
            const float l1 = v1 - __bfloat162float(hv.y);
            *(__nv_bfloat162*)&g_ahi[m1 * DM + n] = hv;
            *(__nv_bfloat162*)&g_alo[m1 * DM + n] = __floats2bfloat162_rn(l0, l1);
        }
    }
}

// ============================================================
// residual + LayerNorm (float4 vectorized)
// ============================================================
__global__ __launch_bounds__(256)
void ln_kernel(const float* __restrict__ P, const float* __restrict__ X,
               const float* __restrict__ gamma, const float* __restrict__ beta,
               float* __restrict__ out) {
    __shared__ float red[9];
    const int row = blockIdx.x;
    const int tid = threadIdx.x;
    const float4 pv = ((const float4*)(P + (size_t)row * DM))[tid];
    const float4 xv = ((const float4*)(X + (size_t)row * DM))[tid];

    float y[4] = { pv.x + xv.x, pv.y + xv.y, pv.z + xv.z, pv.w + xv.w };
    float sum = y[0] + y[1] + y[2] + y[3];
    for (int o = 16; o; o >>= 1) sum += __shfl_xor_sync(0xffffffffu, sum, o);
    const int w = tid >> 5, l = tid & 31;
    if (l == 0) red[w] = sum;
    __syncthreads();
    if (w == 0) {
        float t = (l < 8) ? red[l] : 0.f;
        for (int o = 4; o; o >>= 1) t += __shfl_xor_sync(0xffffffffu, t, o);
        if (l == 0) red[8] = t;
    }
    __syncthreads();
    const float mu = red[8] * (1.f / DM);
    __syncthreads();

    float vs = 0.f;
#pragma unroll
    for (int u = 0; u < 4; u++) { const float d = y[u] - mu; vs += d * d; }
    for (int o = 16; o; o >>= 1) vs += __shfl_xor_sync(0xffffffffu, vs, o);
    if (l == 0) red[w] = vs;
    __syncthreads();
    if (w == 0) {
        float t = (l < 8) ? red[l] : 0.f;
        for (int o = 4; o; o >>= 1) t += __shfl_xor_sync(0xffffffffu, t, o);
        if (l == 0) red[8] = t;
    }
    __syncthreads();
    const float var = red[8] * (1.f / DM);
    const float inv = rsqrtf(var + 1e-5f);

    const float4 gv = ((const float4*)gamma)[tid];
    const float4 bv = ((const float4*)beta)[tid];
    float4 ov;
    ov.x = (y[0] - mu) * inv * gv.x + bv.x;
    ov.y = (y[1] - mu) * inv * gv.y + bv.y;
    ov.z = (y[2] - mu) * inv * gv.z + bv.z;
    ov.w = (y[3] - mu) * inv * gv.w + bv.w;
    ((float4*)(out + (size_t)row * DM))[tid] = ov;
}

// ============================================================
extern "C" void kernel_launch(void* const* d_in, const int* in_sizes, int n_in,
                              void* d_out, int out_size) {
    const float* x     = (const float*)d_in[0];
    const float* wq    = (const float*)d_in[1];
    const float* wk    = (const float*)d_in[2];
    const float* wv    = (const float*)d_in[3];
    const float* wo    = (const float*)d_in[4];
    const float* gamma = (const float*)d_in[5];
    const float* beta  = (const float*)d_in[6];
    float* out = (float*)d_out;

    void *pQKVh, *pQKVl;
    void *pxhi, *pxlo, *pahi, *palo, *pwhi, *pwlo, *pP;
    cudaGetSymbolAddress(&pQKVh, g_QKVhi);
    cudaGetSymbolAddress(&pQKVl, g_QKVlo);
    cudaGetSymbolAddress(&pxhi, g_xhi); cudaGetSymbolAddress(&pxlo, g_xlo);
    cudaGetSymbolAddress(&pahi, g_ahi); cudaGetSymbolAddress(&palo, g_alo);
    cudaGetSymbolAddress(&pwhi, g_wThi); cudaGetSymbolAddress(&pwlo, g_wTlo);
    cudaGetSymbolAddress(&pP, g_proj);

    bf16* xhi = (bf16*)pxhi;  bf16* xlo = (bf16*)pxlo;
    bf16* ahi = (bf16*)pahi;  bf16* alo = (bf16*)palo;
    bf16* whi = (bf16*)pwhi;  bf16* wlo = (bf16*)pwlo;

    // conversions
    cvt_hilo<<<(MROWS * DM) / 256, 256>>>(x, xhi, xlo);
    cvt_wT_all<<<dim3(32, 32, 4), dim3(32, 8)>>>(wq, wk, wv, wo, whi, wlo);

    const int gemm_smem = 2 * 40960;   // 80 KB
    cudaFuncSetAttribute(mma_gemm<0>, cudaFuncAttributeMaxDynamicSharedMemorySize, gemm_smem);
    cudaFuncSetAttribute(mma_gemm<1>, cudaFuncAttributeMaxDynamicSharedMemorySize, gemm_smem);

    // fused QKV projections: grid.z = weight/output slot
    mma_gemm<1><<<dim3(DM / 128, MROWS / 128, 3), 256, gemm_smem>>>(
        xhi, xlo, whi, wlo, nullptr, (bf16*)pQKVh, (bf16*)pQKVl);

    const int attn_smem = 110592;      // Qhi/Qlo (36864) + 2 KV bufs (73728)
    cudaFuncSetAttribute(attn_kernel, cudaFuncAttributeMaxDynamicSharedMemorySize, attn_smem);
    attn_kernel<<<dim3(S_LEN / 128, BATCH * NH), 256, attn_smem>>>();

    // output projection (weight slot 3)
    mma_gemm<0><<<dim3(DM / 128, MROWS / 128, 1), 256, gemm_smem>>>(
        ahi, alo, whi + 3 * (size_t)DM * DM, wlo + 3 * (size_t)DM * DM,
        (float*)pP, nullptr, nullptr);

    ln_kernel<<<MROWS, 256>>>((const float*)pP, x, gamma, beta, out);
}

// round 13
// speedup vs baseline: 1.0198x; 1.0198x over previous
#include <cuda_runtime.h>
#include <cuda_bf16.h>
#include <cstdint>
#include <math.h>

#define S_LEN 2048
#define DM    1024
#define NH    16
#define DH    64
#define BATCH 2
#define MROWS (BATCH * S_LEN)   // 4096
#define QKV_STRIDE ((size_t)MROWS * DM)

using bf16 = __nv_bfloat16;

// ================= helpers =================
__device__ __forceinline__ uint32_t smem_to_u32(const void* p) {
    uint32_t a;
    asm("{ .reg .u64 t; cvta.to.shared.u64 t, %1; cvt.u32.u64 %0, t; }" : "=r"(a) : "l"(p));
    return a;
}
__device__ __forceinline__ void cp_async16(uint32_t saddr, const void* gaddr) {
    asm volatile("cp.async.cg.shared.global [%0], [%1], 16;" :: "r"(saddr), "l"(gaddr));
}
__device__ __forceinline__ void ldsm_x4(uint32_t* r, uint32_t addr) {
    asm volatile("ldmatrix.sync.aligned.m8n8.x4.shared.b16 {%0,%1,%2,%3}, [%4];"
                 : "=r"(r[0]), "=r"(r[1]), "=r"(r[2]), "=r"(r[3]) : "r"(addr));
}
__device__ __forceinline__ void ldsm_x2(uint32_t* r, uint32_t addr) {
    asm volatile("ldmatrix.sync.aligned.m8n8.x2.shared.b16 {%0,%1}, [%2];"
                 : "=r"(r[0]), "=r"(r[1]) : "r"(addr));
}
__device__ __forceinline__ void ldsm_x2t(uint32_t* r, uint32_t addr) {
    asm volatile("ldmatrix.sync.aligned.m8n8.x2.trans.shared.b16 {%0,%1}, [%2];"
                 : "=r"(r[0]), "=r"(r[1]) : "r"(addr));
}
// D += A(16x16 bf16, row) * B(16x8 bf16, col), fp32 acc
__device__ __forceinline__ void mma16816(float* d, const uint32_t* a, const uint32_t* b) {
    asm volatile(
        "mma.sync.aligned.m16n8k16.row.col.f32.bf16.bf16.f32 "
        "{%0,%1,%2,%3}, {%4,%5,%6,%7}, {%8,%9}, {%0,%1,%2,%3};\n"
        : "+f"(d[0]), "+f"(d[1]), "+f"(d[2]), "+f"(d[3])
        : "r"(a[0]), "r"(a[1]), "r"(a[2]), "r"(a[3]), "r"(b[0]), "r"(b[1]));
}
// pack two fp32 into bf16x2 (hi part) plus residual bf16x2 (lo part)
__device__ __forceinline__ void pack_pair(float p0, float p1, uint32_t& hi, uint32_t& lo) {
    __nv_bfloat162 h = __floats2bfloat162_rn(p0, p1);   // .x = p0 (low half)
    hi = *(uint32_t*)&h;
    const float l0 = p0 - __bfloat162float(h.x);
    const float l1 = p1 - __bfloat162float(h.y);
    __nv_bfloat162 l = __floats2bfloat162_rn(l0, l1);
    lo = *(uint32_t*)&l;
}

// ---- scratch (device globals) ----
__device__ bf16 g_QKVhi[3][BATCH * NH * S_LEN * DH];   // [B,H,S,Dh] x {Q,K,V}
__device__ bf16 g_QKVlo[3][BATCH * NH * S_LEN * DH];
__device__ bf16 g_xhi[MROWS * DM];
__device__ bf16 g_xlo[MROWS * DM];
__device__ bf16 g_ahi[MROWS * DM];
__device__ bf16 g_alo[MROWS * DM];
__device__ bf16 g_wThi[4][DM * DM];   // q,k,v,o  ([N,K] layout)
__device__ bf16 g_wTlo[4][DM * DM];
__device__ float g_proj[MROWS * DM];

// ============================================================
// fp32 -> bf16 hi/lo split (same layout)
// ============================================================
__global__ __launch_bounds__(256)
void cvt_hilo(const float* __restrict__ in, bf16* __restrict__ hi,
              bf16* __restrict__ lo) {
    const int i = blockIdx.x * 256 + threadIdx.x;
    const float v = in[i];
    const bf16 h = __float2bfloat16(v);
    hi[i] = h;
    lo[i] = __float2bfloat16(v - __bfloat162float(h));
}

// all 4 weights [K=1024, N=1024] fp32 -> wT hi/lo [N, K] bf16, smem transpose
__global__ __launch_bounds__(256)
void cvt_wT_all(const float* __restrict__ w0, const float* __restrict__ w1,
                const float* __restrict__ w2, const float* __restrict__ w3,
                bf16* __restrict__ hiT, bf16* __restrict__ loT) {
    __shared__ float t[32][33];
    const float* ws[4] = { w0, w1, w2, w3 };
    const int z = blockIdx.z;
    const float* w = ws[z];
    const int bn = blockIdx.x * 32, bk = blockIdx.y * 32;
    const int tx = threadIdx.x, ty = threadIdx.y;   // block (32, 8)
#pragma unroll
    for (int i = 0; i < 32; i += 8)
        t[ty + i][tx] = w[(size_t)(bk + ty + i) * DM + bn + tx];
    __syncthreads();
    const size_t zoff = (size_t)z * DM * DM;
#pragma unroll
    for (int i = 0; i < 32; i += 8) {
        const float v = t[tx][ty + i];                 // = w[bk+tx][bn+ty+i]
        const bf16 h = __float2bfloat16(v);
        const size_t o = zoff + (size_t)(bn + ty + i) * DM + bk + tx;
        hiT[o] = h;
        loT[o] = __float2bfloat16(v - __bfloat162float(h));
    }
}

// ============================================================
// HMMA split-bf16 GEMM: C[4096,1024] = A @ B^T (B stored [N,K]).
// D = Ahi*Bhi + Ahi*Blo + Alo*Bhi, fp32 accumulate.
// 128x128 block tile, K-tile 32, 8 warps (4x2), warp 32x64.
// cp.async double buffer. smem row stride 40 bf16 (80B).
// blockIdx.z selects weight slot (and output slot in MODE 1).
// MODE 0: fp32 C row-major.  MODE 1: bf16 hi/lo scatter to [B,H,S,Dh].
// __launch_bounds__(256,2): 2 CTAs/SM.
// ============================================================
template <int MODE>
__global__ __launch_bounds__(256, 2)
void mma_gemm(const bf16* __restrict__ Ahi, const bf16* __restrict__ Alo,
              const bf16* __restrict__ BhiB, const bf16* __restrict__ BloB,
              float* __restrict__ C, bf16* __restrict__ ChiB, bf16* __restrict__ CloB)
{
    extern __shared__ char smd[];
    const int tid = threadIdx.x;
    const int lane = tid & 31, wid = tid >> 5;
    const int wm = wid & 3, wn = wid >> 2;            // 4 x 2 warp grid
    const int m0 = blockIdx.y * 128, n0 = blockIdx.x * 128;
    const int z = blockIdx.z;
    const uint32_t sb = smem_to_u32(smd);

    const bf16* Bhi = BhiB + (size_t)z * DM * DM;
    const bf16* Blo = BloB + (size_t)z * DM * DM;
    const bf16* srcs[4] = { Ahi + (size_t)m0 * DM, Alo + (size_t)m0 * DM,
                            Bhi + (size_t)n0 * DM, Blo + (size_t)n0 * DM };

    auto prefetch = [&](int kt) {
        const uint32_t bb = sb + (kt & 1) * 40960;
        const int k0 = kt * 32;
#pragma unroll
        for (int t = 0; t < 4; t++) {
            const bf16* s = srcs[t] + k0;
            const uint32_t tb = bb + t * 10240;
#pragma unroll
            for (int i = 0; i < 2; i++) {
                const int idx = i * 256 + tid;
                const int r = idx >> 2, c = idx & 3;
                cp_async16(tb + r * 80 + c * 16, s + (size_t)r * DM + c * 8);
            }
        }
        asm volatile("cp.async.commit_group;");
    };

    prefetch(0);
    prefetch(1);

    float acc[2][8][4];
#pragma unroll
    for (int mt = 0; mt < 2; mt++)
#pragma unroll
        for (int nt = 0; nt < 8; nt++)
#pragma unroll
            for (int e = 0; e < 4; e++) acc[mt][nt][e] = 0.f;

    const int KT = DM / 32;   // 32
    for (int kt = 0; kt < KT; kt++) {
        if (kt == KT - 1) asm volatile("cp.async.wait_group 0;" ::: "memory");
        else              asm volatile("cp.async.wait_group 1;" ::: "memory");
        __syncthreads();
        const uint32_t bb = sb + (kt & 1) * 40960;
#pragma unroll
        for (int ks = 0; ks < 2; ks++) {
            const int kk = ks * 16;
            uint32_t ah[2][4], al[2][4];
            const uint32_t acol = (uint32_t)(kk + (lane >> 4) * 8) * 2;
#pragma unroll
            for (int mt = 0; mt < 2; mt++) {
                const uint32_t ra = bb + (uint32_t)(wm * 32 + mt * 16 + (lane & 15)) * 80 + acol;
                ldsm_x4(ah[mt], ra);
                ldsm_x4(al[mt], ra + 10240);
            }
#pragma unroll
            for (int nt = 0; nt < 8; nt++) {
                uint32_t bhf[2], blf[2];
                const uint32_t rb = bb + 20480
                    + (uint32_t)(wn * 64 + nt * 8 + (lane & 7)) * 80
                    + (uint32_t)(kk + ((lane >> 3) & 1) * 8) * 2;
                ldsm_x2(bhf, rb);
                ldsm_x2(blf, rb + 10240);
#pragma unroll
                for (int mt = 0; mt < 2; mt++) {
                    mma16816(acc[mt][nt], ah[mt], bhf);
                    mma16816(acc[mt][nt], ah[mt], blf);
                    mma16816(acc[mt][nt], al[mt], bhf);
                }
            }
        }
        __syncthreads();
        if (kt + 2 < KT) prefetch(kt + 2);
    }

    bf16* Chi = (MODE == 1) ? ChiB + (size_t)z * QKV_STRIDE : nullptr;
    bf16* Clo = (MODE == 1) ? CloB + (size_t)z * QKV_STRIDE : nullptr;

#pragma unroll
    for (int mt = 0; mt < 2; mt++)
#pragma unroll
    for (int nt = 0; nt < 8; nt++) {
        const int r0 = m0 + wm * 32 + mt * 16 + (lane >> 2);
        const int c0 = n0 + wn * 64 + nt * 8 + (lane & 3) * 2;
#pragma unroll
        for (int e = 0; e < 4; e++) {
            const int r = r0 + (e >> 1) * 8;
            const int c = c0 + (e & 1);
            const float v = acc[mt][nt][e];
            if (MODE == 0) {
                C[(size_t)r * DM + c] = v;
            } else {
                const int b = r >> 11, s = r & 2047;
                const int h = c >> 6, d = c & 63;
                const size_t o = (((size_t)(b * NH + h)) * S_LEN + s) * DH + d;
                const bf16 hv = __float2bfloat16(v);
                Chi[o] = hv;
                Clo[o] = __float2bfloat16(v - __bfloat162float(hv));
            }
        }
    }
}

// ============================================================
// FA2-style HMMA flash attention: BM=128, BN=64, Dh=64, 4 warps.
// Each warp: 32 query rows (2 m-tiles) x full 64 kv cols x Dh=64.
// K/V fragments loaded ONCE per (ks,nt) and reused across both
// m-tiles -> halves the smem crossbar traffic per MMA (the R12
// bottleneck). 128 threads/CTA; regs float free (~200), smem caps
// occupancy at 2 CTAs/SM.
// ============================================================
__global__ __launch_bounds__(128)
void attn_kernel() {
    extern __shared__ char smd[];
    const int tid = threadIdx.x, lane = tid & 31, wid = tid >> 5;   // 4 warps
    const int qt = (int)gridDim.x - 1 - (int)blockIdx.x;   // heavy tiles first
    const int bh = blockIdx.y;
    const int b = bh >> 4, h = bh & 15;
    const int q0 = qt * 128;
    const int groupID = lane >> 2, tid4 = lane & 3;
    const uint32_t sb = smem_to_u32(smd);
    const uint32_t QHo = 0;                        // Qhi 128x144B, Qlo at +18432
    const uint32_t KV0 = 36864, KVSZ = 36864;      // per buf: Khi,Klo,Vhi,Vlo (64x144B each)
    const int nkt = 2 * qt + 2;

    const size_t base_off = (size_t)bh * S_LEN * DH;

    // Q hi/lo loads (128 threads: 8 iters over 1024 16B-chunks per array-pair)
    {
        const bf16* qh = g_QKVhi[0] + base_off + (size_t)q0 * DH;
        const bf16* ql = g_QKVlo[0] + base_off + (size_t)q0 * DH;
#pragma unroll
        for (int i = 0; i < 8; i++) {
            const int idx = i * 128 + tid;
            const int r = idx >> 3, c = idx & 7;
            cp_async16(sb + QHo + r * 144 + c * 16, qh + r * 64 + c * 8);
            cp_async16(sb + QHo + 18432 + r * 144 + c * 16, ql + r * 64 + c * 8);
        }
    }
    auto kvload = [&](int kt) {
        const uint32_t bb = sb + KV0 + (kt & 1) * KVSZ;
        const size_t off = base_off + (size_t)kt * 64 * DH;
        const bf16* srcs[4] = { g_QKVhi[1] + off, g_QKVlo[1] + off,
                                g_QKVhi[2] + off, g_QKVlo[2] + off };
#pragma unroll
        for (int t = 0; t < 4; t++) {
            const uint32_t tb = bb + t * 9216;
            const bf16* s = srcs[t];
#pragma unroll
            for (int i = 0; i < 4; i++) {
                const int idx = i * 128 + tid;
                const int r = idx >> 3, c = idx & 7;
                cp_async16(tb + r * 144 + c * 16, s + r * 64 + c * 8);
            }
        }
        asm volatile("cp.async.commit_group;");
    };
    kvload(0);           // G0 = Q + KV0
    kvload(1);           // G1 = KV1   (nkt >= 2 always)
    asm volatile("cp.async.wait_group 1;" ::: "memory");
    __syncthreads();

    // Hoist Q-hi fragments for both m-tiles; Q-lo reloaded per ks
    uint32_t qrow_addr[2];
#pragma unroll
    for (int mt = 0; mt < 2; mt++)
        qrow_addr[mt] = sb + QHo + (uint32_t)(wid * 32 + mt * 16 + (lane & 15)) * 144
                        + (uint32_t)((lane >> 4) * 8) * 2;
    uint32_t qhf[2][4][4];
#pragma unroll
    for (int mt = 0; mt < 2; mt++)
#pragma unroll
        for (int ks = 0; ks < 4; ks++) ldsm_x4(qhf[mt][ks], qrow_addr[mt] + ks * 32);

    float rm[2][2], rl[2][2];
#pragma unroll
    for (int mt = 0; mt < 2; mt++) { rm[mt][0] = rm[mt][1] = -1e30f; rl[mt][0] = rl[mt][1] = 0.f; }
    float oacc[2][8][4];
#pragma unroll
    for (int mt = 0; mt < 2; mt++)
#pragma unroll
        for (int nt = 0; nt < 8; nt++)
#pragma unroll
            for (int e = 0; e < 4; e++) oacc[mt][nt][e] = 0.f;

    for (int kt = 0; kt < nkt; kt++) {
        const uint32_t kb = sb + KV0 + (kt & 1) * KVSZ;
        const uint32_t vb = kb + 18432;

        // ---- S = Q @ K^T (3-pass split), 32x64 per warp ----
        float sacc[2][8][4];
#pragma unroll
        for (int mt = 0; mt < 2; mt++)
#pragma unroll
            for (int nt = 0; nt < 8; nt++)
#pragma unroll
                for (int e = 0; e < 4; e++) sacc[mt][nt][e] = 0.f;

#pragma unroll
        for (int ks = 0; ks < 4; ks++) {
            uint32_t qlf[2][4];
            ldsm_x4(qlf[0], qrow_addr[0] + 18432 + ks * 32);
            ldsm_x4(qlf[1], qrow_addr[1] + 18432 + ks * 32);
#pragma unroll
            for (int nt = 0; nt < 8; nt++) {
                uint32_t khf[2], klf[2];
                const uint32_t rb = kb + (uint32_t)(nt * 8 + (lane & 7)) * 144
                                    + (uint32_t)(ks * 16 + ((lane >> 3) & 1) * 8) * 2;
                ldsm_x2(khf, rb);
                ldsm_x2(klf, rb + 9216);
#pragma unroll
                for (int mt = 0; mt < 2; mt++) {
                    mma16816(sacc[mt][nt], qhf[mt][ks], khf);
                    mma16816(sacc[mt][nt], qhf[mt][ks], klf);
                    mma16816(sacc[mt][nt], qlf[mt], khf);
                }
            }
        }

        // ---- scale + causal mask + online softmax per m-tile ----
#pragma unroll
        for (int mt = 0; mt < 2; mt++) {
            const int row0 = q0 + wid * 32 + mt * 16 + groupID;
#pragma unroll
            for (int nt = 0; nt < 8; nt++) {
                const int c0 = kt * 64 + nt * 8 + tid4 * 2;
#pragma unroll
                for (int e = 0; e < 4; e++) {
                    const int col = c0 + (e & 1);
                    const int row = row0 + ((e >> 1) << 3);
                    const float v = sacc[mt][nt][e] * 0.125f;
                    sacc[mt][nt][e] = (col > row) ? -10000000.0f : v;
                }
            }
            float mx0 = rm[mt][0], mx1 = rm[mt][1];
#pragma unroll
            for (int nt = 0; nt < 8; nt++) {
                mx0 = fmaxf(mx0, fmaxf(sacc[mt][nt][0], sacc[mt][nt][1]));
                mx1 = fmaxf(mx1, fmaxf(sacc[mt][nt][2], sacc[mt][nt][3]));
            }
            mx0 = fmaxf(mx0, __shfl_xor_sync(0xffffffffu, mx0, 1));
            mx0 = fmaxf(mx0, __shfl_xor_sync(0xffffffffu, mx0, 2));
            mx1 = fmaxf(mx1, __shfl_xor_sync(0xffffffffu, mx1, 1));
            mx1 = fmaxf(mx1, __shfl_xor_sync(0xffffffffu, mx1, 2));
            float s0 = 0.f, s1 = 0.f;
#pragma unroll
            for (int nt = 0; nt < 8; nt++) {
                sacc[mt][nt][0] = __expf(sacc[mt][nt][0] - mx0); s0 += sacc[mt][nt][0];
                sacc[mt][nt][1] = __expf(sacc[mt][nt][1] - mx0); s0 += sacc[mt][nt][1];
                sacc[mt][nt][2] = __expf(sacc[mt][nt][2] - mx1); s1 += sacc[mt][nt][2];
                sacc[mt][nt][3] = __expf(sacc[mt][nt][3] - mx1); s1 += sacc[mt][nt][3];
            }
            s0 += __shfl_xor_sync(0xffffffffu, s0, 1);
            s0 += __shfl_xor_sync(0xffffffffu, s0, 2);
            s1 += __shfl_xor_sync(0xffffffffu, s1, 1);
            s1 += __shfl_xor_sync(0xffffffffu, s1, 2);
            const float sc0 = __expf(rm[mt][0] - mx0), sc1 = __expf(rm[mt][1] - mx1);
            rl[mt][0] = rl[mt][0] * sc0 + s0;  rl[mt][1] = rl[mt][1] * sc1 + s1;
            rm[mt][0] = mx0;  rm[mt][1] = mx1;
#pragma unroll
            for (int nt = 0; nt < 8; nt++) {
                oacc[mt][nt][0] *= sc0; oacc[mt][nt][1] *= sc0;
                oacc[mt][nt][2] *= sc1; oacc[mt][nt][3] *= sc1;
            }
        }

        // ---- O += P @ V: repack C-frag -> A-frag; V frags shared by both m-tiles ----
#pragma unroll
        for (int j = 0; j < 4; j++) {
            uint32_t ph[2][4], pl[2][4];
#pragma unroll
            for (int mt = 0; mt < 2; mt++) {
                pack_pair(sacc[mt][2 * j][0],     sacc[mt][2 * j][1],     ph[mt][0], pl[mt][0]);
                pack_pair(sacc[mt][2 * j][2],     sacc[mt][2 * j][3],     ph[mt][1], pl[mt][1]);
                pack_pair(sacc[mt][2 * j + 1][0], sacc[mt][2 * j + 1][1], ph[mt][2], pl[mt][2]);
                pack_pair(sacc[mt][2 * j + 1][2], sacc[mt][2 * j + 1][3], ph[mt][3], pl[mt][3]);
            }
#pragma unroll
            for (int nt = 0; nt < 8; nt++) {
                uint32_t vhf[2], vlf[2];
                const uint32_t rb = vb + (uint32_t)(j * 16 + (lane & 15)) * 144
                                    + (uint32_t)(nt * 8) * 2;
                ldsm_x2t(vhf, rb);
                ldsm_x2t(vlf, rb + 9216);
#pragma unroll
                for (int mt = 0; mt < 2; mt++) {
                    mma16816(oacc[mt][nt], ph[mt], vhf);
                    mma16816(oacc[mt][nt], ph[mt], vlf);
                    mma16816(oacc[mt][nt], pl[mt], vhf);
                }
            }
        }

        // ---- pipeline next KV tile ----
        if (kt + 1 < nkt) {
            __syncthreads();   // all warps done reading buf (kt&1)
            if (kt + 2 < nkt) {
                kvload(kt + 2);
                asm volatile("cp.async.wait_group 1;" ::: "memory");
            } else {
                asm volatile("cp.async.wait_group 0;" ::: "memory");
            }
        }
    }

    // ---- epilogue: O / l  -> bf16 hi/lo merged-head layout ----
#pragma unroll
    for (int mt = 0; mt < 2; mt++) {
        const float inv0 = 1.f / rl[mt][0], inv1 = 1.f / rl[mt][1];
        const size_t m0 = (size_t)b * S_LEN + q0 + wid * 32 + mt * 16 + groupID;
        const size_t m1 = m0 + 8;
#pragma unroll
        for (int nt = 0; nt < 8; nt++) {
            const int n = h * 64 + nt * 8 + tid4 * 2;
            {
                const float v0 = oacc[mt][nt][0] * inv0, v1 = oacc[mt][nt][1] * inv0;
                __nv_bfloat162 hv = __floats2bfloat162_rn(v0, v1);
                const float l0 = v0 - __bfloat162float(hv.x);
                const float l1 = v1 - __bfloat162float(hv.y);
                *(__nv_bfloat162*)&g_ahi[m0 * DM + n] = hv;
                *(__nv_bfloat162*)&g_alo[m0 * DM + n] = __floats2bfloat162_rn(l0, l1);
            }
            {
                const float v0 = oacc[mt][nt][2] * inv1, v1 = oacc[mt][nt][3] * inv1;
                __nv_bfloat162 hv = __floats2bfloat162_rn(v0, v1);
                const float l0 = v0 - __bfloat162float(hv.x);
                const float l1 = v1 - __bfloat162float(hv.y);
                *(__nv_bfloat162*)&g_ahi[m1 * DM + n] = hv;
                *(__nv_bfloat162*)&g_alo[m1 * DM + n] = __floats2bfloat162_rn(l0, l1);
            }
        }
    }
}

// ============================================================
// residual + LayerNorm (float4 vectorized)
// ============================================================
__global__ __launch_bounds__(256)
void ln_kernel(const float* __restrict__ P, const float* __restrict__ X,
               const float* __restrict__ gamma, const float* __restrict__ beta,
               float* __restrict__ out) {
    __shared__ float red[9];
    const int row = blockIdx.x;
    const int tid = threadIdx.x;
    const float4 pv = ((const float4*)(P + (size_t)row * DM))[tid];
    const float4 xv = ((const float4*)(X + (size_t)row * DM))[tid];

    float y[4] = { pv.x + xv.x, pv.y + xv.y, pv.z + xv.z, pv.w + xv.w };
    float sum = y[0] + y[1] + y[2] + y[3];
    for (int o = 16; o; o >>= 1) sum += __shfl_xor_sync(0xffffffffu, sum, o);
    const int w = tid >> 5, l = tid & 31;
    if (l == 0) red[w] = sum;
    __syncthreads();
    if (w == 0) {
        float t = (l < 8) ? red[l] : 0.f;
        for (int o = 4; o; o >>= 1) t += __shfl_xor_sync(0xffffffffu, t, o);
        if (l == 0) red[8] = t;
    }
    __syncthreads();
    const float mu = red[8] * (1.f / DM);
    __syncthreads();

    float vs = 0.f;
#pragma unroll
    for (int u = 0; u < 4; u++) { const float d = y[u] - mu; vs += d * d; }
    for (int o = 16; o; o >>= 1) vs += __shfl_xor_sync(0xffffffffu, vs, o);
    if (l == 0) red[w] = vs;
    __syncthreads();
    if (w == 0) {
        float t = (l < 8) ? red[l] : 0.f;
        for (int o = 4; o; o >>= 1) t += __shfl_xor_sync(0xffffffffu, t, o);
        if (l == 0) red[8] = t;
    }
    __syncthreads();
    const float var = red[8] * (1.f / DM);
    const float inv = rsqrtf(var + 1e-5f);

    const float4 gv = ((const float4*)gamma)[tid];
    const float4 bv = ((const float4*)beta)[tid];
    float4 ov;
    ov.x = (y[0] - mu) * inv * gv.x + bv.x;
    ov.y = (y[1] - mu) * inv * gv.y + bv.y;
    ov.z = (y[2] - mu) * inv * gv.z + bv.z;
    ov.w = (y[3] - mu) * inv * gv.w + bv.w;
    ((float4*)(out + (size_t)row * DM))[tid] = ov;
}

// ============================================================
extern "C" void kernel_launch(void* const* d_in, const int* in_sizes, int n_in,
                              void* d_out, int out_size) {
    const float* x     = (const float*)d_in[0];
    const float* wq    = (const float*)d_in[1];
    const float* wk    = (const float*)d_in[2];
    const float* wv    = (const float*)d_in[3];
    const float* wo    = (const float*)d_in[4];
    const float* gamma = (const float*)d_in[5];
    const float* beta  = (const float*)d_in[6];
    float* out = (float*)d_out;

    void *pQKVh, *pQKVl;
    void *pxhi, *pxlo, *pahi, *palo, *pwhi, *pwlo, *pP;
    cudaGetSymbolAddress(&pQKVh, g_QKVhi);
    cudaGetSymbolAddress(&pQKVl, g_QKVlo);
    cudaGetSymbolAddress(&pxhi, g_xhi); cudaGetSymbolAddress(&pxlo, g_xlo);
    cudaGetSymbolAddress(&pahi, g_ahi); cudaGetSymbolAddress(&palo, g_alo);
    cudaGetSymbolAddress(&pwhi, g_wThi); cudaGetSymbolAddress(&pwlo, g_wTlo);
    cudaGetSymbolAddress(&pP, g_proj);

    bf16* xhi = (bf16*)pxhi;  bf16* xlo = (bf16*)pxlo;
    bf16* ahi = (bf16*)pahi;  bf16* alo = (bf16*)palo;
    bf16* whi = (bf16*)pwhi;  bf16* wlo = (bf16*)pwlo;

    // conversions
    cvt_hilo<<<(MROWS * DM) / 256, 256>>>(x, xhi, xlo);
    cvt_wT_all<<<dim3(32, 32, 4), dim3(32, 8)>>>(wq, wk, wv, wo, whi, wlo);

    const int gemm_smem = 2 * 40960;   // 80 KB
    cudaFuncSetAttribute(mma_gemm<0>, cudaFuncAttributeMaxDynamicSharedMemorySize, gemm_smem);
    cudaFuncSetAttribute(mma_gemm<1>, cudaFuncAttributeMaxDynamicSharedMemorySize, gemm_smem);

    // fused QKV projections: grid.z = weight/output slot
    mma_gemm<1><<<dim3(DM / 128, MROWS / 128, 3), 256, gemm_smem>>>(
        xhi, xlo, whi, wlo, nullptr, (bf16*)pQKVh, (bf16*)pQKVl);

    const int attn_smem = 110592;      // Qhi/Qlo (36864) + 2 KV bufs (73728)
    cudaFuncSetAttribute(attn_kernel, cudaFuncAttributeMaxDynamicSharedMemorySize, attn_smem);
    attn_kernel<<<dim3(S_LEN / 128, BATCH * NH), 128, attn_smem>>>();

    // output projection (weight slot 3)
    mma_gemm<0><<<dim3(DM / 128, MROWS / 128, 1), 256, gemm_smem>>>(
        ahi, alo, whi + 3 * (size_t)DM * DM, wlo + 3 * (size_t)DM * DM,
        (float*)pP, nullptr, nullptr);

    ln_kernel<<<MROWS, 256>>>((const float*)pP, x, gamma, beta, out);
}

// round 14
// speedup vs baseline: 2.1795x; 2.1372x over previous
#include <cuda_runtime.h>
#include <cuda_fp16.h>
#include <cstdint>
#include <math.h>

#define S_LEN 2048
#define DM    1024
#define NH    16
#define DH    64
#define BATCH 2
#define MROWS (BATCH * S_LEN)   // 4096
#define QKV_STRIDE ((size_t)MROWS * DM)

using f16 = __half;

// ================= helpers =================
__device__ __forceinline__ uint32_t smem_to_u32(const void* p) {
    uint32_t a;
    asm("{ .reg .u64 t; cvta.to.shared.u64 t, %1; cvt.u32.u64 %0, t; }" : "=r"(a) : "l"(p));
    return a;
}
__device__ __forceinline__ void cp_async16(uint32_t saddr, const void* gaddr) {
    asm volatile("cp.async.cg.shared.global [%0], [%1], 16;" :: "r"(saddr), "l"(gaddr));
}
__device__ __forceinline__ void ldsm_x4(uint32_t* r, uint32_t addr) {
    asm volatile("ldmatrix.sync.aligned.m8n8.x4.shared.b16 {%0,%1,%2,%3}, [%4];"
                 : "=r"(r[0]), "=r"(r[1]), "=r"(r[2]), "=r"(r[3]) : "r"(addr));
}
__device__ __forceinline__ void ldsm_x2(uint32_t* r, uint32_t addr) {
    asm volatile("ldmatrix.sync.aligned.m8n8.x2.shared.b16 {%0,%1}, [%2];"
                 : "=r"(r[0]), "=r"(r[1]) : "r"(addr));
}
__device__ __forceinline__ void ldsm_x2t(uint32_t* r, uint32_t addr) {
    asm volatile("ldmatrix.sync.aligned.m8n8.x2.trans.shared.b16 {%0,%1}, [%2];"
                 : "=r"(r[0]), "=r"(r[1]) : "r"(addr));
}
// D += A(16x16 f16, row) * B(16x8 f16, col), fp32 acc
__device__ __forceinline__ void mma16816(float* d, const uint32_t* a, const uint32_t* b) {
    asm volatile(
        "mma.sync.aligned.m16n8k16.row.col.f32.f16.f16.f32 "
        "{%0,%1,%2,%3}, {%4,%5,%6,%7}, {%8,%9}, {%0,%1,%2,%3};\n"
        : "+f"(d[0]), "+f"(d[1]), "+f"(d[2]), "+f"(d[3])
        : "r"(a[0]), "r"(a[1]), "r"(a[2]), "r"(a[3]), "r"(b[0]), "r"(b[1]));
}

// ---- scratch (device globals) ----
__device__ f16 g_QKV[3][BATCH * NH * S_LEN * DH];   // [B,H,S,Dh] x {Q,K,V} (Q pre-scaled by 0.125)
__device__ f16 g_x16[MROWS * DM];
__device__ f16 g_a16[MROWS * DM];
__device__ f16 g_wT[4][DM * DM];     // q,k,v,o  ([N,K] layout)
__device__ float g_proj[MROWS * DM];

// ============================================================
// fp32 -> fp16
// ============================================================
__global__ __launch_bounds__(256)
void cvt_x(const float* __restrict__ in, f16* __restrict__ out) {
    const int i = blockIdx.x * 256 + threadIdx.x;
    const float2 v = ((const float2*)in)[i];
    ((__half2*)out)[i] = __floats2half2_rn(v.x, v.y);
}

// all 4 weights [K=1024, N=1024] fp32 -> wT [N, K] fp16, smem transpose
__global__ __launch_bounds__(256)
void cvt_wT_all(const float* __restrict__ w0, const float* __restrict__ w1,
                const float* __restrict__ w2, const float* __restrict__ w3,
                f16* __restrict__ wT) {
    __shared__ float t[32][33];
    const float* ws[4] = { w0, w1, w2, w3 };
    const int z = blockIdx.z;
    const float* w = ws[z];
    const int bn = blockIdx.x * 32, bk = blockIdx.y * 32;
    const int tx = threadIdx.x, ty = threadIdx.y;   // block (32, 8)
#pragma unroll
    for (int i = 0; i < 32; i += 8)
        t[ty + i][tx] = w[(size_t)(bk + ty + i) * DM + bn + tx];
    __syncthreads();
    const size_t zoff = (size_t)z * DM * DM;
#pragma unroll
    for (int i = 0; i < 32; i += 8)
        wT[zoff + (size_t)(bn + ty + i) * DM + bk + tx] = __float2half(t[tx][ty + i]);
}

// ============================================================
// HMMA fp16 GEMM: C[4096,1024] = A @ B^T (B stored [N,K]).
// Single pass, fp32 accumulate. 128x128 tile, K-tile 32,
// 8 warps (4x2), warp 32x64, cp.async double buffer.
// Row stride 80B (32 f16 = 64B + 16B pad).
// MODE 0: fp32 C row-major.  MODE 1: f16 scatter to [B,H,S,Dh]
//         (z==0 pre-scales by 0.125 for attention).
// ============================================================
template <int MODE>
__global__ __launch_bounds__(256, 2)
void mma_gemm(const f16* __restrict__ A, const f16* __restrict__ Ball,
              float* __restrict__ C, f16* __restrict__ C16B)
{
    extern __shared__ char smd[];
    const int tid = threadIdx.x;
    const int lane = tid & 31, wid = tid >> 5;
    const int wm = wid & 3, wn = wid >> 2;            // 4 x 2 warp grid
    const int m0 = blockIdx.y * 128, n0 = blockIdx.x * 128;
    const int z = blockIdx.z;
    const uint32_t sb = smem_to_u32(smd);

    const f16* B = Ball + (size_t)z * DM * DM;
    const f16* srcs[2] = { A + (size_t)m0 * DM, B + (size_t)n0 * DM };

    auto prefetch = [&](int kt) {
        const uint32_t bb = sb + (kt & 1) * 20480;
        const int k0 = kt * 32;
#pragma unroll
        for (int t = 0; t < 2; t++) {
            const f16* s = srcs[t] + k0;
            const uint32_t tb = bb + t * 10240;
#pragma unroll
            for (int i = 0; i < 2; i++) {
                const int idx = i * 256 + tid;
                const int r = idx >> 2, c = idx & 3;
                cp_async16(tb + r * 80 + c * 16, s + (size_t)r * DM + c * 8);
            }
        }
        asm volatile("cp.async.commit_group;");
    };

    prefetch(0);
    prefetch(1);

    float acc[2][8][4];
#pragma unroll
    for (int mt = 0; mt < 2; mt++)
#pragma unroll
        for (int nt = 0; nt < 8; nt++)
#pragma unroll
            for (int e = 0; e < 4; e++) acc[mt][nt][e] = 0.f;

    const int KT = DM / 32;   // 32
    for (int kt = 0; kt < KT; kt++) {
        if (kt == KT - 1) asm volatile("cp.async.wait_group 0;" ::: "memory");
        else              asm volatile("cp.async.wait_group 1;" ::: "memory");
        __syncthreads();
        const uint32_t bb = sb + (kt & 1) * 20480;
#pragma unroll
        for (int ks = 0; ks < 2; ks++) {
            const int kk = ks * 16;
            uint32_t ah[2][4];
            const uint32_t acol = (uint32_t)(kk + (lane >> 4) * 8) * 2;
#pragma unroll
            for (int mt = 0; mt < 2; mt++)
                ldsm_x4(ah[mt], bb + (uint32_t)(wm * 32 + mt * 16 + (lane & 15)) * 80 + acol);
#pragma unroll
            for (int nt = 0; nt < 8; nt++) {
                uint32_t bf[2];
                const uint32_t rb = bb + 10240
                    + (uint32_t)(wn * 64 + nt * 8 + (lane & 7)) * 80
                    + (uint32_t)(kk + ((lane >> 3) & 1) * 8) * 2;
                ldsm_x2(bf, rb);
#pragma unroll
                for (int mt = 0; mt < 2; mt++) mma16816(acc[mt][nt], ah[mt], bf);
            }
        }
        __syncthreads();
        if (kt + 2 < KT) prefetch(kt + 2);
    }

    f16* C16 = (MODE == 1) ? C16B + (size_t)z * QKV_STRIDE : nullptr;
    const float oscl = (MODE == 1 && z == 0) ? 0.125f : 1.0f;

#pragma unroll
    for (int mt = 0; mt < 2; mt++)
#pragma unroll
    for (int nt = 0; nt < 8; nt++) {
        const int r0 = m0 + wm * 32 + mt * 16 + (lane >> 2);
        const int c0 = n0 + wn * 64 + nt * 8 + (lane & 3) * 2;
#pragma unroll
        for (int e = 0; e < 4; e++) {
            const int r = r0 + (e >> 1) * 8;
            const int c = c0 + (e & 1);
            const float v = acc[mt][nt][e];
            if (MODE == 0) {
                C[(size_t)r * DM + c] = v;
            } else {
                const int b = r >> 11, s = r & 2047;
                const int h = c >> 6, d = c & 63;
                C16[(((size_t)(b * NH + h)) * S_LEN + s) * DH + d] = __float2half(v * oscl);
            }
        }
    }
}

// ============================================================
// FA2-style fp16 flash attention: BM=128, BN=64, Dh=64, 4 warps,
// each warp 32 query rows (2 m-tiles). Single-pass fp16 MMA,
// fp32 softmax in registers, P repacked C-frag -> A-frag.
// Q pre-scaled by 0.125 at projection time.
// smem: Q 18432 + 2 KV bufs (18432 each) = 55296 B.
// ============================================================
__global__ __launch_bounds__(128)
void attn_kernel() {
    extern __shared__ char smd[];
    const int tid = threadIdx.x, lane = tid & 31, wid = tid >> 5;   // 4 warps
    const int qt = (int)gridDim.x - 1 - (int)blockIdx.x;   // heavy tiles first
    const int bh = blockIdx.y;
    const int b = bh >> 4, h = bh & 15;
    const int q0 = qt * 128;
    const int groupID = lane >> 2, tid4 = lane & 3;
    const uint32_t sb = smem_to_u32(smd);
    const uint32_t KV0 = 18432, KVSZ = 18432;      // per buf: K(9216), V(9216); rows 144B
    const int nkt = 2 * qt + 2;

    const size_t base_off = (size_t)bh * S_LEN * DH;

    // Q load
    {
        const f16* q = g_QKV[0] + base_off + (size_t)q0 * DH;
#pragma unroll
        for (int i = 0; i < 8; i++) {
            const int idx = i * 128 + tid;
            const int r = idx >> 3, c = idx & 7;
            cp_async16(sb + r * 144 + c * 16, q + r * 64 + c * 8);
        }
    }
    auto kvload = [&](int kt) {
        const uint32_t bb = sb + KV0 + (kt & 1) * KVSZ;
        const size_t off = base_off + (size_t)kt * 64 * DH;
        const f16* srcs[2] = { g_QKV[1] + off, g_QKV[2] + off };
#pragma unroll
        for (int t = 0; t < 2; t++) {
            const uint32_t tb = bb + t * 9216;
            const f16* s = srcs[t];
#pragma unroll
            for (int i = 0; i < 4; i++) {
                const int idx = i * 128 + tid;
                const int r = idx >> 3, c = idx & 7;
                cp_async16(tb + r * 144 + c * 16, s + r * 64 + c * 8);
            }
        }
        asm volatile("cp.async.commit_group;");
    };
    kvload(0);
    kvload(1);
    asm volatile("cp.async.wait_group 1;" ::: "memory");
    __syncthreads();

    // Hoist Q fragments for both m-tiles (fp16, single array)
    uint32_t qf[2][4][4];
#pragma unroll
    for (int mt = 0; mt < 2; mt++) {
        const uint32_t ra = sb + (uint32_t)(wid * 32 + mt * 16 + (lane & 15)) * 144
                            + (uint32_t)((lane >> 4) * 8) * 2;
#pragma unroll
        for (int ks = 0; ks < 4; ks++) ldsm_x4(qf[mt][ks], ra + ks * 32);
    }

    float rm[2][2], rl[2][2];
#pragma unroll
    for (int mt = 0; mt < 2; mt++) { rm[mt][0] = rm[mt][1] = -1e30f; rl[mt][0] = rl[mt][1] = 0.f; }
    float oacc[2][8][4];
#pragma unroll
    for (int mt = 0; mt < 2; mt++)
#pragma unroll
        for (int nt = 0; nt < 8; nt++)
#pragma unroll
            for (int e = 0; e < 4; e++) oacc[mt][nt][e] = 0.f;

    for (int kt = 0; kt < nkt; kt++) {
        const uint32_t kb = sb + KV0 + (kt & 1) * KVSZ;
        const uint32_t vb = kb + 9216;

        // ---- S = Q @ K^T, 32x64 per warp ----
        float sacc[2][8][4];
#pragma unroll
        for (int mt = 0; mt < 2; mt++)
#pragma unroll
            for (int nt = 0; nt < 8; nt++)
#pragma unroll
                for (int e = 0; e < 4; e++) sacc[mt][nt][e] = 0.f;

#pragma unroll
        for (int ks = 0; ks < 4; ks++) {
#pragma unroll
            for (int nt = 0; nt < 8; nt++) {
                uint32_t kf[2];
                const uint32_t rb = kb + (uint32_t)(nt * 8 + (lane & 7)) * 144
                                    + (uint32_t)(ks * 16 + ((lane >> 3) & 1) * 8) * 2;
                ldsm_x2(kf, rb);
#pragma unroll
                for (int mt = 0; mt < 2; mt++) mma16816(sacc[mt][nt], qf[mt][ks], kf);
            }
        }

        // ---- causal mask + online softmax per m-tile (Q pre-scaled) ----
#pragma unroll
        for (int mt = 0; mt < 2; mt++) {
            const int row0 = q0 + wid * 32 + mt * 16 + groupID;
#pragma unroll
            for (int nt = 0; nt < 8; nt++) {
                const int c0 = kt * 64 + nt * 8 + tid4 * 2;
#pragma unroll
                for (int e = 0; e < 4; e++) {
                    const int col = c0 + (e & 1);
                    const int row = row0 + ((e >> 1) << 3);
                    if (col > row) sacc[mt][nt][e] = -10000000.0f;
                }
            }
            float mx0 = rm[mt][0], mx1 = rm[mt][1];
#pragma unroll
            for (int nt = 0; nt < 8; nt++) {
                mx0 = fmaxf(mx0, fmaxf(sacc[mt][nt][0], sacc[mt][nt][1]));
                mx1 = fmaxf(mx1, fmaxf(sacc[mt][nt][2], sacc[mt][nt][3]));
            }
            mx0 = fmaxf(mx0, __shfl_xor_sync(0xffffffffu, mx0, 1));
            mx0 = fmaxf(mx0, __shfl_xor_sync(0xffffffffu, mx0, 2));
            mx1 = fmaxf(mx1, __shfl_xor_sync(0xffffffffu, mx1, 1));
            mx1 = fmaxf(mx1, __shfl_xor_sync(0xffffffffu, mx1, 2));
            float s0 = 0.f, s1 = 0.f;
#pragma unroll
            for (int nt = 0; nt < 8; nt++) {
                sacc[mt][nt][0] = __expf(sacc[mt][nt][0] - mx0); s0 += sacc[mt][nt][0];
                sacc[mt][nt][1] = __expf(sacc[mt][nt][1] - mx0); s0 += sacc[mt][nt][1];
                sacc[mt][nt][2] = __expf(sacc[mt][nt][2] - mx1); s1 += sacc[mt][nt][2];
                sacc[mt][nt][3] = __expf(sacc[mt][nt][3] - mx1); s1 += sacc[mt][nt][3];
            }
            s0 += __shfl_xor_sync(0xffffffffu, s0, 1);
            s0 += __shfl_xor_sync(0xffffffffu, s0, 2);
            s1 += __shfl_xor_sync(0xffffffffu, s1, 1);
            s1 += __shfl_xor_sync(0xffffffffu, s1, 2);
            const float sc0 = __expf(rm[mt][0] - mx0), sc1 = __expf(rm[mt][1] - mx1);
            rl[mt][0] = rl[mt][0] * sc0 + s0;  rl[mt][1] = rl[mt][1] * sc1 + s1;
            rm[mt][0] = mx0;  rm[mt][1] = mx1;
#pragma unroll
            for (int nt = 0; nt < 8; nt++) {
                oacc[mt][nt][0] *= sc0; oacc[mt][nt][1] *= sc0;
                oacc[mt][nt][2] *= sc1; oacc[mt][nt][3] *= sc1;
            }
        }

        // ---- O += P @ V: repack C-frag -> A-frag; V frags shared across m-tiles ----
#pragma unroll
        for (int j = 0; j < 4; j++) {
            uint32_t pf[2][4];
#pragma unroll
            for (int mt = 0; mt < 2; mt++) {
                __half2 h0 = __floats2half2_rn(sacc[mt][2 * j][0],     sacc[mt][2 * j][1]);
                __half2 h1 = __floats2half2_rn(sacc[mt][2 * j][2],     sacc[mt][2 * j][3]);
                __half2 h2 = __floats2half2_rn(sacc[mt][2 * j + 1][0], sacc[mt][2 * j + 1][1]);
                __half2 h3 = __floats2half2_rn(sacc[mt][2 * j + 1][2], sacc[mt][2 * j + 1][3]);
                pf[mt][0] = *(uint32_t*)&h0;  pf[mt][1] = *(uint32_t*)&h1;
                pf[mt][2] = *(uint32_t*)&h2;  pf[mt][3] = *(uint32_t*)&h3;
            }
#pragma unroll
            for (int nt = 0; nt < 8; nt++) {
                uint32_t vf[2];
                const uint32_t rb = vb + (uint32_t)(j * 16 + (lane & 15)) * 144
                                    + (uint32_t)(nt * 8) * 2;
                ldsm_x2t(vf, rb);
#pragma unroll
                for (int mt = 0; mt < 2; mt++) mma16816(oacc[mt][nt], pf[mt], vf);
            }
        }

        // ---- pipeline next KV tile ----
        if (kt + 1 < nkt) {
            __syncthreads();
            if (kt + 2 < nkt) {
                kvload(kt + 2);
                asm volatile("cp.async.wait_group 1;" ::: "memory");
            } else {
                asm volatile("cp.async.wait_group 0;" ::: "memory");
            }
        }
    }

    // ---- epilogue: O / l  -> fp16 merged-head layout ----
#pragma unroll
    for (int mt = 0; mt < 2; mt++) {
        const float inv0 = 1.f / rl[mt][0], inv1 = 1.f / rl[mt][1];
        const size_t m0 = (size_t)b * S_LEN + q0 + wid * 32 + mt * 16 + groupID;
        const size_t m1 = m0 + 8;
#pragma unroll
        for (int nt = 0; nt < 8; nt++) {
            const int n = h * 64 + nt * 8 + tid4 * 2;
            *(__half2*)&g_a16[m0 * DM + n] =
                __floats2half2_rn(oacc[mt][nt][0] * inv0, oacc[mt][nt][1] * inv0);
            *(__half2*)&g_a16[m1 * DM + n] =
                __floats2half2_rn(oacc[mt][nt][2] * inv1, oacc[mt][nt][3] * inv1);
        }
    }
}

// ============================================================
// residual + LayerNorm (float4 vectorized)
// ============================================================
__global__ __launch_bounds__(256)
void ln_kernel(const float* __restrict__ P, const float* __restrict__ X,
               const float* __restrict__ gamma, const float* __restrict__ beta,
               float* __restrict__ out) {
    __shared__ float red[9];
    const int row = blockIdx.x;
    const int tid = threadIdx.x;
    const float4 pv = ((const float4*)(P + (size_t)row * DM))[tid];
    const float4 xv = ((const float4*)(X + (size_t)row * DM))[tid];

    float y[4] = { pv.x + xv.x, pv.y + xv.y, pv.z + xv.z, pv.w + xv.w };
    float sum = y[0] + y[1] + y[2] + y[3];
    for (int o = 16; o; o >>= 1) sum += __shfl_xor_sync(0xffffffffu, sum, o);
    const int w = tid >> 5, l = tid & 31;
    if (l == 0) red[w] = sum;
    __syncthreads();
    if (w == 0) {
        float t = (l < 8) ? red[l] : 0.f;
        for (int o = 4; o; o >>= 1) t += __shfl_xor_sync(0xffffffffu, t, o);
        if (l == 0) red[8] = t;
    }
    __syncthreads();
    const float mu = red[8] * (1.f / DM);
    __syncthreads();

    float vs = 0.f;
#pragma unroll
    for (int u = 0; u < 4; u++) { const float d = y[u] - mu; vs += d * d; }
    for (int o = 16; o; o >>= 1) vs += __shfl_xor_sync(0xffffffffu, vs, o);
    if (l == 0) red[w] = vs;
    __syncthreads();
    if (w == 0) {
        float t = (l < 8) ? red[l] : 0.f;
        for (int o = 4; o; o >>= 1) t += __shfl_xor_sync(0xffffffffu, t, o);
        if (l == 0) red[8] = t;
    }
    __syncthreads();
    const float var = red[8] * (1.f / DM);
    const float inv = rsqrtf(var + 1e-5f);

    const float4 gv = ((const float4*)gamma)[tid];
    const float4 bv = ((const float4*)beta)[tid];
    float4 ov;
    ov.x = (y[0] - mu) * inv * gv.x + bv.x;
    ov.y = (y[1] - mu) * inv * gv.y + bv.y;
    ov.z = (y[2] - mu) * inv * gv.z + bv.z;
    ov.w = (y[3] - mu) * inv * gv.w + bv.w;
    ((float4*)(out + (size_t)row * DM))[tid] = ov;
}

// ============================================================
extern "C" void kernel_launch(void* const* d_in, const int* in_sizes, int n_in,
                              void* d_out, int out_size) {
    const float* x     = (const float*)d_in[0];
    const float* wq    = (const float*)d_in[1];
    const float* wk    = (const float*)d_in[2];
    const float* wv    = (const float*)d_in[3];
    const float* wo    = (const float*)d_in[4];
    const float* gamma = (const float*)d_in[5];
    const float* beta  = (const float*)d_in[6];
    float* out = (float*)d_out;

    void *pQKV, *px16, *pa16, *pwT, *pP;
    cudaGetSymbolAddress(&pQKV, g_QKV);
    cudaGetSymbolAddress(&px16, g_x16);
    cudaGetSymbolAddress(&pa16, g_a16);
    cudaGetSymbolAddress(&pwT, g_wT);
    cudaGetSymbolAddress(&pP, g_proj);

    f16* x16 = (f16*)px16;
    f16* a16 = (f16*)pa16;
    f16* wT  = (f16*)pwT;

    // conversions
    cvt_x<<<(MROWS * DM / 2) / 256, 256>>>(x, x16);
    cvt_wT_all<<<dim3(32, 32, 4), dim3(32, 8)>>>(wq, wk, wv, wo, wT);

    const int gemm_smem = 2 * 20480;   // 40 KB
    cudaFuncSetAttribute(mma_gemm<0>, cudaFuncAttributeMaxDynamicSharedMemorySize, gemm_smem);
    cudaFuncSetAttribute(mma_gemm<1>, cudaFuncAttributeMaxDynamicSharedMemorySize, gemm_smem);

    // fused QKV projections: grid.z = weight/output slot (z=0 Q pre-scaled by 0.125)
    mma_gemm<1><<<dim3(DM / 128, MROWS / 128, 3), 256, gemm_smem>>>(
        x16, wT, nullptr, (f16*)pQKV);

    const int attn_smem = 55296;       // Q (18432) + 2 KV bufs (36864)
    cudaFuncSetAttribute(attn_kernel, cudaFuncAttributeMaxDynamicSharedMemorySize, attn_smem);
    attn_kernel<<<dim3(S_LEN / 128, BATCH * NH), 128, attn_smem>>>();

    // output projection (weight slot 3)
    mma_gemm<0><<<dim3(DM / 128, MROWS / 128, 1), 256, gemm_smem>>>(
        a16, wT + 3 * (size_t)DM * DM, (float*)pP, nullptr);

    ln_kernel<<<MROWS, 256>>>((const float*)pP, x, gamma, beta, out);
}

// round 15
// speedup vs baseline: 2.2724x; 1.0426x over previous
#include <cuda_runtime.h>
#include <cuda_fp16.h>
#include <cstdint>
#include <math.h>

#define S_LEN 2048
#define DM    1024
#define NH    16
#define DH    64
#define BATCH 2
#define MROWS (BATCH * S_LEN)   // 4096
#define QKV_STRIDE ((size_t)MROWS * DM)

using f16 = __half;

// ================= helpers =================
__device__ __forceinline__ uint32_t smem_to_u32(const void* p) {
    uint32_t a;
    asm("{ .reg .u64 t; cvta.to.shared.u64 t, %1; cvt.u32.u64 %0, t; }" : "=r"(a) : "l"(p));
    return a;
}
__device__ __forceinline__ void cp_async16(uint32_t saddr, const void* gaddr) {
    asm volatile("cp.async.cg.shared.global [%0], [%1], 16;" :: "r"(saddr), "l"(gaddr));
}
__device__ __forceinline__ void ldsm_x4(uint32_t* r, uint32_t addr) {
    asm volatile("ldmatrix.sync.aligned.m8n8.x4.shared.b16 {%0,%1,%2,%3}, [%4];"
                 : "=r"(r[0]), "=r"(r[1]), "=r"(r[2]), "=r"(r[3]) : "r"(addr));
}
__device__ __forceinline__ void ldsm_x2(uint32_t* r, uint32_t addr) {
    asm volatile("ldmatrix.sync.aligned.m8n8.x2.shared.b16 {%0,%1}, [%2];"
                 : "=r"(r[0]), "=r"(r[1]) : "r"(addr));
}
__device__ __forceinline__ void ldsm_x2t(uint32_t* r, uint32_t addr) {
    asm volatile("ldmatrix.sync.aligned.m8n8.x2.trans.shared.b16 {%0,%1}, [%2];"
                 : "=r"(r[0]), "=r"(r[1]) : "r"(addr));
}
// D += A(16x16 f16, row) * B(16x8 f16, col), fp32 acc
__device__ __forceinline__ void mma16816(float* d, const uint32_t* a, const uint32_t* b) {
    asm volatile(
        "mma.sync.aligned.m16n8k16.row.col.f32.f16.f16.f32 "
        "{%0,%1,%2,%3}, {%4,%5,%6,%7}, {%8,%9}, {%0,%1,%2,%3};\n"
        : "+f"(d[0]), "+f"(d[1]), "+f"(d[2]), "+f"(d[3])
        : "r"(a[0]), "r"(a[1]), "r"(a[2]), "r"(a[3]), "r"(b[0]), "r"(b[1]));
}

// ---- scratch (device globals) ----
__device__ f16 g_QKV[3][BATCH * NH * S_LEN * DH];   // [B,H,S,Dh] x {Q,K,V} (Q pre-scaled by 0.125*log2e)
__device__ f16 g_x16[MROWS * DM];
__device__ f16 g_a16[MROWS * DM];
__device__ f16 g_wT[4][DM * DM];     // q,k,v,o  ([N,K] layout)
__device__ float g_proj[MROWS * DM];

// ============================================================
// fp32 -> fp16
// ============================================================
__global__ __launch_bounds__(256)
void cvt_x(const float* __restrict__ in, f16* __restrict__ out) {
    const int i = blockIdx.x * 256 + threadIdx.x;
    const float2 v = ((const float2*)in)[i];
    ((__half2*)out)[i] = __floats2half2_rn(v.x, v.y);
}

// all 4 weights [K=1024, N=1024] fp32 -> wT [N, K] fp16, smem transpose
__global__ __launch_bounds__(256)
void cvt_wT_all(const float* __restrict__ w0, const float* __restrict__ w1,
                const float* __restrict__ w2, const float* __restrict__ w3,
                f16* __restrict__ wT) {
    __shared__ float t[32][33];
    const float* ws[4] = { w0, w1, w2, w3 };
    const int z = blockIdx.z;
    const float* w = ws[z];
    const int bn = blockIdx.x * 32, bk = blockIdx.y * 32;
    const int tx = threadIdx.x, ty = threadIdx.y;   // block (32, 8)
#pragma unroll
    for (int i = 0; i < 32; i += 8)
        t[ty + i][tx] = w[(size_t)(bk + ty + i) * DM + bn + tx];
    __syncthreads();
    const size_t zoff = (size_t)z * DM * DM;
#pragma unroll
    for (int i = 0; i < 32; i += 8)
        wT[zoff + (size_t)(bn + ty + i) * DM + bk + tx] = __float2half(t[tx][ty + i]);
}

// ============================================================
// HMMA fp16 GEMM: C[4096,1024] = A @ B^T (B stored [N,K]).
// Single pass, fp32 accumulate. 128x128 tile, K-tile 32,
// 8 warps (4x2), warp 32x64, cp.async 3-stage pipeline
// (buffers kt%3), ONE __syncthreads per k-iter.
// MODE 0: fp32 C row-major.  MODE 1: f16 scatter to [B,H,S,Dh]
//         (z==0 pre-scales by 0.125*log2e for base-2 attention).
// ============================================================
template <int MODE>
__global__ __launch_bounds__(256, 2)
void mma_gemm(const f16* __restrict__ A, const f16* __restrict__ Ball,
              float* __restrict__ C, f16* __restrict__ C16B)
{
    extern __shared__ char smd[];
    const int tid = threadIdx.x;
    const int lane = tid & 31, wid = tid >> 5;
    const int wm = wid & 3, wn = wid >> 2;            // 4 x 2 warp grid
    const int m0 = blockIdx.y * 128, n0 = blockIdx.x * 128;
    const int z = blockIdx.z;
    const uint32_t sb = smem_to_u32(smd);

    const f16* B = Ball + (size_t)z * DM * DM;
    const f16* srcs[2] = { A + (size_t)m0 * DM, B + (size_t)n0 * DM };

    auto prefetch = [&](int kt) {
        const uint32_t bb = sb + (kt % 3) * 20480;
        const int k0 = kt * 32;
#pragma unroll
        for (int t = 0; t < 2; t++) {
            const f16* s = srcs[t] + k0;
            const uint32_t tb = bb + t * 10240;
#pragma unroll
            for (int i = 0; i < 2; i++) {
                const int idx = i * 256 + tid;
                const int r = idx >> 2, c = idx & 3;
                cp_async16(tb + r * 80 + c * 16, s + (size_t)r * DM + c * 8);
            }
        }
        asm volatile("cp.async.commit_group;");
    };

    prefetch(0);
    prefetch(1);

    float acc[2][8][4];
#pragma unroll
    for (int mt = 0; mt < 2; mt++)
#pragma unroll
        for (int nt = 0; nt < 8; nt++)
#pragma unroll
            for (int e = 0; e < 4; e++) acc[mt][nt][e] = 0.f;

    const int KT = DM / 32;   // 32
    for (int kt = 0; kt < KT; kt++) {
        if (kt == KT - 1) asm volatile("cp.async.wait_group 0;" ::: "memory");
        else              asm volatile("cp.async.wait_group 1;" ::: "memory");
        __syncthreads();   // orders: buffer (kt+2)%3 free (compute kt-1 done everywhere)
        if (kt + 2 < KT) prefetch(kt + 2);
        const uint32_t bb = sb + (kt % 3) * 20480;
#pragma unroll
        for (int ks = 0; ks < 2; ks++) {
            const int kk = ks * 16;
            uint32_t ah[2][4];
            const uint32_t acol = (uint32_t)(kk + (lane >> 4) * 8) * 2;
#pragma unroll
            for (int mt = 0; mt < 2; mt++)
                ldsm_x4(ah[mt], bb + (uint32_t)(wm * 32 + mt * 16 + (lane & 15)) * 80 + acol);
#pragma unroll
            for (int nt = 0; nt < 8; nt++) {
                uint32_t bf[2];
                const uint32_t rb = bb + 10240
                    + (uint32_t)(wn * 64 + nt * 8 + (lane & 7)) * 80
                    + (uint32_t)(kk + ((lane >> 3) & 1) * 8) * 2;
                ldsm_x2(bf, rb);
#pragma unroll
                for (int mt = 0; mt < 2; mt++) mma16816(acc[mt][nt], ah[mt], bf);
            }
        }
    }

    f16* C16 = (MODE == 1) ? C16B + (size_t)z * QKV_STRIDE : nullptr;
    const float oscl = (MODE == 1 && z == 0) ? 0.125f * 1.44269504f : 1.0f;

#pragma unroll
    for (int mt = 0; mt < 2; mt++)
#pragma unroll
    for (int nt = 0; nt < 8; nt++) {
        const int r0 = m0 + wm * 32 + mt * 16 + (lane >> 2);
        const int c0 = n0 + wn * 64 + nt * 8 + (lane & 3) * 2;
#pragma unroll
        for (int e = 0; e < 4; e++) {
            const int r = r0 + (e >> 1) * 8;
            const int c = c0 + (e & 1);
            const float v = acc[mt][nt][e];
            if (MODE == 0) {
                C[(size_t)r * DM + c] = v;
            } else {
                const int b = r >> 11, s = r & 2047;
                const int h = c >> 6, d = c & 63;
                C16[(((size_t)(b * NH + h)) * S_LEN + s) * DH + d] = __float2half(v * oscl);
            }
        }
    }
}

// ============================================================
// FA2-style fp16 flash attention: BM=128, BN=64, Dh=64, 4 warps,
// each warp 32 query rows (2 m-tiles). Base-2 online softmax
// (Q pre-scaled by 0.125*log2e; exp2f = bare MUFU.EX2).
// Causal mask applied ONLY on the last two kv-tiles (the only
// tiles that can straddle the diagonal for BM=128/BN=64).
// ============================================================
__global__ __launch_bounds__(128)
void attn_kernel() {
    extern __shared__ char smd[];
    const int tid = threadIdx.x, lane = tid & 31, wid = tid >> 5;   // 4 warps
    const int qt = (int)gridDim.x - 1 - (int)blockIdx.x;   // heavy tiles first
    const int bh = blockIdx.y;
    const int b = bh >> 4, h = bh & 15;
    const int q0 = qt * 128;
    const int groupID = lane >> 2, tid4 = lane & 3;
    const uint32_t sb = smem_to_u32(smd);
    const uint32_t KV0 = 18432, KVSZ = 18432;      // per buf: K(9216), V(9216); rows 144B
    const int nkt = 2 * qt + 2;

    const size_t base_off = (size_t)bh * S_LEN * DH;

    // Q load
    {
        const f16* q = g_QKV[0] + base_off + (size_t)q0 * DH;
#pragma unroll
        for (int i = 0; i < 8; i++) {
            const int idx = i * 128 + tid;
            const int r = idx >> 3, c = idx & 7;
            cp_async16(sb + r * 144 + c * 16, q + r * 64 + c * 8);
        }
    }
    auto kvload = [&](int kt) {
        const uint32_t bb = sb + KV0 + (kt & 1) * KVSZ;
        const size_t off = base_off + (size_t)kt * 64 * DH;
        const f16* srcs[2] = { g_QKV[1] + off, g_QKV[2] + off };
#pragma unroll
        for (int t = 0; t < 2; t++) {
            const uint32_t tb = bb + t * 9216;
            const f16* s = srcs[t];
#pragma unroll
            for (int i = 0; i < 4; i++) {
                const int idx = i * 128 + tid;
                const int r = idx >> 3, c = idx & 7;
                cp_async16(tb + r * 144 + c * 16, s + r * 64 + c * 8);
            }
        }
        asm volatile("cp.async.commit_group;");
    };
    kvload(0);
    kvload(1);
    asm volatile("cp.async.wait_group 1;" ::: "memory");
    __syncthreads();

    // Hoist Q fragments for both m-tiles
    uint32_t qf[2][4][4];
#pragma unroll
    for (int mt = 0; mt < 2; mt++) {
        const uint32_t ra = sb + (uint32_t)(wid * 32 + mt * 16 + (lane & 15)) * 144
                            + (uint32_t)((lane >> 4) * 8) * 2;
#pragma unroll
        for (int ks = 0; ks < 4; ks++) ldsm_x4(qf[mt][ks], ra + ks * 32);
    }

    float rm[2][2], rl[2][2];
#pragma unroll
    for (int mt = 0; mt < 2; mt++) { rm[mt][0] = rm[mt][1] = -1e30f; rl[mt][0] = rl[mt][1] = 0.f; }
    float oacc[2][8][4];
#pragma unroll
    for (int mt = 0; mt < 2; mt++)
#pragma unroll
        for (int nt = 0; nt < 8; nt++)
#pragma unroll
            for (int e = 0; e < 4; e++) oacc[mt][nt][e] = 0.f;

    for (int kt = 0; kt < nkt; kt++) {
        const uint32_t kb = sb + KV0 + (kt & 1) * KVSZ;
        const uint32_t vb = kb + 9216;

        // ---- S = Q @ K^T, 32x64 per warp ----
        float sacc[2][8][4];
#pragma unroll
        for (int mt = 0; mt < 2; mt++)
#pragma unroll
            for (int nt = 0; nt < 8; nt++)
#pragma unroll
                for (int e = 0; e < 4; e++) sacc[mt][nt][e] = 0.f;

#pragma unroll
        for (int ks = 0; ks < 4; ks++) {
#pragma unroll
            for (int nt = 0; nt < 8; nt++) {
                uint32_t kf[2];
                const uint32_t rb = kb + (uint32_t)(nt * 8 + (lane & 7)) * 144
                                    + (uint32_t)(ks * 16 + ((lane >> 3) & 1) * 8) * 2;
                ldsm_x2(kf, rb);
#pragma unroll
                for (int mt = 0; mt < 2; mt++) mma16816(sacc[mt][nt], qf[mt][ks], kf);
            }
        }

        // ---- causal mask only on diagonal-straddling tiles ----
        if (kt >= nkt - 2) {
#pragma unroll
            for (int mt = 0; mt < 2; mt++) {
                const int row0 = q0 + wid * 32 + mt * 16 + groupID;
#pragma unroll
                for (int nt = 0; nt < 8; nt++) {
                    const int c0 = kt * 64 + nt * 8 + tid4 * 2;
#pragma unroll
                    for (int e = 0; e < 4; e++) {
                        const int col = c0 + (e & 1);
                        const int row = row0 + ((e >> 1) << 3);
                        if (col > row) sacc[mt][nt][e] = -10000000.0f;
                    }
                }
            }
        }

        // ---- base-2 online softmax per m-tile ----
#pragma unroll
        for (int mt = 0; mt < 2; mt++) {
            float mx0 = rm[mt][0], mx1 = rm[mt][1];
#pragma unroll
            for (int nt = 0; nt < 8; nt++) {
                mx0 = fmaxf(mx0, fmaxf(sacc[mt][nt][0], sacc[mt][nt][1]));
                mx1 = fmaxf(mx1, fmaxf(sacc[mt][nt][2], sacc[mt][nt][3]));
            }
            mx0 = fmaxf(mx0, __shfl_xor_sync(0xffffffffu, mx0, 1));
            mx0 = fmaxf(mx0, __shfl_xor_sync(0xffffffffu, mx0, 2));
            mx1 = fmaxf(mx1, __shfl_xor_sync(0xffffffffu, mx1, 1));
            mx1 = fmaxf(mx1, __shfl_xor_sync(0xffffffffu, mx1, 2));
            float s0 = 0.f, s1 = 0.f;
#pragma unroll
            for (int nt = 0; nt < 8; nt++) {
                sacc[mt][nt][0] = exp2f(sacc[mt][nt][0] - mx0); s0 += sacc[mt][nt][0];
                sacc[mt][nt][1] = exp2f(sacc[mt][nt][1] - mx0); s0 += sacc[mt][nt][1];
                sacc[mt][nt][2] = exp2f(sacc[mt][nt][2] - mx1); s1 += sacc[mt][nt][2];
                sacc[mt][nt][3] = exp2f(sacc[mt][nt][3] - mx1); s1 += sacc[mt][nt][3];
            }
            s0 += __shfl_xor_sync(0xffffffffu, s0, 1);
            s0 += __shfl_xor_sync(0xffffffffu, s0, 2);
            s1 += __shfl_xor_sync(0xffffffffu, s1, 1);
            s1 += __shfl_xor_sync(0xffffffffu, s1, 2);
            const float sc0 = exp2f(rm[mt][0] - mx0), sc1 = exp2f(rm[mt][1] - mx1);
            rl[mt][0] = rl[mt][0] * sc0 + s0;  rl[mt][1] = rl[mt][1] * sc1 + s1;
            rm[mt][0] = mx0;  rm[mt][1] = mx1;
#pragma unroll
            for (int nt = 0; nt < 8; nt++) {
                oacc[mt][nt][0] *= sc0; oacc[mt][nt][1] *= sc0;
                oacc[mt][nt][2] *= sc1; oacc[mt][nt][3] *= sc1;
            }
        }

        // ---- O += P @ V: repack C-frag -> A-frag; V frags shared across m-tiles ----
#pragma unroll
        for (int j = 0; j < 4; j++) {
            uint32_t pf[2][4];
#pragma unroll
            for (int mt = 0; mt < 2; mt++) {
                __half2 h0 = __floats2half2_rn(sacc[mt][2 * j][0],     sacc[mt][2 * j][1]);
                __half2 h1 = __floats2half2_rn(sacc[mt][2 * j][2],     sacc[mt][2 * j][3]);
                __half2 h2 = __floats2half2_rn(sacc[mt][2 * j + 1][0], sacc[mt][2 * j + 1][1]);
                __half2 h3 = __floats2half2_rn(sacc[mt][2 * j + 1][2], sacc[mt][2 * j + 1][3]);
                pf[mt][0] = *(uint32_t*)&h0;  pf[mt][1] = *(uint32_t*)&h1;
                pf[mt][2] = *(uint32_t*)&h2;  pf[mt][3] = *(uint32_t*)&h3;
            }
#pragma unroll
            for (int nt = 0; nt < 8; nt++) {
                uint32_t vf[2];
                const uint32_t rb = vb + (uint32_t)(j * 16 + (lane & 15)) * 144
                                    + (uint32_t)(nt * 8) * 2;
                ldsm_x2t(vf, rb);
#pragma unroll
                for (int mt = 0; mt < 2; mt++) mma16816(oacc[mt][nt], pf[mt], vf);
            }
        }

        // ---- pipeline next KV tile ----
        if (kt + 1 < nkt) {
            __syncthreads();
            if (kt + 2 < nkt) {
                kvload(kt + 2);
                asm volatile("cp.async.wait_group 1;" ::: "memory");
            } else {
                asm volatile("cp.async.wait_group 0;" ::: "memory");
            }
        }
    }

    // ---- epilogue: O / l  -> fp16 merged-head layout ----
#pragma unroll
    for (int mt = 0; mt < 2; mt++) {
        const float inv0 = 1.f / rl[mt][0], inv1 = 1.f / rl[mt][1];
        const size_t m0 = (size_t)b * S_LEN + q0 + wid * 32 + mt * 16 + groupID;
        const size_t m1 = m0 + 8;
#pragma unroll
        for (int nt = 0; nt < 8; nt++) {
            const int n = h * 64 + nt * 8 + tid4 * 2;
            *(__half2*)&g_a16[m0 * DM + n] =
                __floats2half2_rn(oacc[mt][nt][0] * inv0, oacc[mt][nt][1] * inv0);
            *(__half2*)&g_a16[m1 * DM + n] =
                __floats2half2_rn(oacc[mt][nt][2] * inv1, oacc[mt][nt][3] * inv1);
        }
    }
}

// ============================================================
// residual + LayerNorm (float4 vectorized)
// ============================================================
__global__ __launch_bounds__(256)
void ln_kernel(const float* __restrict__ P, const float* __restrict__ X,
               const float* __restrict__ gamma, const float* __restrict__ beta,
               float* __restrict__ out) {
    __shared__ float red[9];
    const int row = blockIdx.x;
    const int tid = threadIdx.x;
    const float4 pv = ((const float4*)(P + (size_t)row * DM))[tid];
    const float4 xv = ((const float4*)(X + (size_t)row * DM))[tid];

    float y[4] = { pv.x + xv.x, pv.y + xv.y, pv.z + xv.z, pv.w + xv.w };
    float sum = y[0] + y[1] + y[2] + y[3];
    for (int o = 16; o; o >>= 1) sum += __shfl_xor_sync(0xffffffffu, sum, o);
    const int w = tid >> 5, l = tid & 31;
    if (l == 0) red[w] = sum;
    __syncthreads();
    if (w == 0) {
        float t = (l < 8) ? red[l] : 0.f;
        for (int o = 4; o; o >>= 1) t += __shfl_xor_sync(0xffffffffu, t, o);
        if (l == 0) red[8] = t;
    }
    __syncthreads();
    const float mu = red[8] * (1.f / DM);
    __syncthreads();

    float vs = 0.f;
#pragma unroll
    for (int u = 0; u < 4; u++) { const float d = y[u] - mu; vs += d * d; }
    for (int o = 16; o; o >>= 1) vs += __shfl_xor_sync(0xffffffffu, vs, o);
    if (l == 0) red[w] = vs;
    __syncthreads();
    if (w == 0) {
        float t = (l < 8) ? red[l] : 0.f;
        for (int o = 4; o; o >>= 1) t += __shfl_xor_sync(0xffffffffu, t, o);
        if (l == 0) red[8] = t;
    }
    __syncthreads();
    const float var = red[8] * (1.f / DM);
    const float inv = rsqrtf(var + 1e-5f);

    const float4 gv = ((const float4*)gamma)[tid];
    const float4 bv = ((const float4*)beta)[tid];
    float4 ov;
    ov.x = (y[0] - mu) * inv * gv.x + bv.x;
    ov.y = (y[1] - mu) * inv * gv.y + bv.y;
    ov.z = (y[2] - mu) * inv * gv.z + bv.z;
    ov.w = (y[3] - mu) * inv * gv.w + bv.w;
    ((float4*)(out + (size_t)row * DM))[tid] = ov;
}

// ============================================================
extern "C" void kernel_launch(void* const* d_in, const int* in_sizes, int n_in,
                              void* d_out, int out_size) {
    const float* x     = (const float*)d_in[0];
    const float* wq    = (const float*)d_in[1];
    const float* wk    = (const float*)d_in[2];
    const float* wv    = (const float*)d_in[3];
    const float* wo    = (const float*)d_in[4];
    const float* gamma = (const float*)d_in[5];
    const float* beta  = (const float*)d_in[6];
    float* out = (float*)d_out;

    void *pQKV, *px16, *pa16, *pwT, *pP;
    cudaGetSymbolAddress(&pQKV, g_QKV);
    cudaGetSymbolAddress(&px16, g_x16);
    cudaGetSymbolAddress(&pa16, g_a16);
    cudaGetSymbolAddress(&pwT, g_wT);
    cudaGetSymbolAddress(&pP, g_proj);

    f16* x16 = (f16*)px16;
    f16* a16 = (f16*)pa16;
    f16* wT  = (f16*)pwT;

    // conversions
    cvt_x<<<(MROWS * DM / 2) / 256, 256>>>(x, x16);
    cvt_wT_all<<<dim3(32, 32, 4), dim3(32, 8)>>>(wq, wk, wv, wo, wT);

    const int gemm_smem = 3 * 20480;   // 60 KB (3-stage)
    cudaFuncSetAttribute(mma_gemm<0>, cudaFuncAttributeMaxDynamicSharedMemorySize, gemm_smem);
    cudaFuncSetAttribute(mma_gemm<1>, cudaFuncAttributeMaxDynamicSharedMemorySize, gemm_smem);

    // fused QKV projections: grid.z = weight/output slot (z=0 Q pre-scaled by 0.125*log2e)
    mma_gemm<1><<<dim3(DM / 128, MROWS / 128, 3), 256, gemm_smem>>>(
        x16, wT, nullptr, (f16*)pQKV);

    const int attn_smem = 55296;       // Q (18432) + 2 KV bufs (36864)
    cudaFuncSetAttribute(attn_kernel, cudaFuncAttributeMaxDynamicSharedMemorySize, attn_smem);
    attn_kernel<<<dim3(S_LEN / 128, BATCH * NH), 128, attn_smem>>>();

    // output projection (weight slot 3)
    mma_gemm<0><<<dim3(DM / 128, MROWS / 128, 1), 256, gemm_smem>>>(
        a16, wT + 3 * (size_t)DM * DM, (float*)pP, nullptr);

    ln_kernel<<<MROWS, 256>>>((const float*)pP, x, gamma, beta, out);
}

// round 16
// speedup vs baseline: 2.4323x; 1.0704x over previous
#include <cuda_runtime.h>
#include <cuda_fp16.h>
#include <cstdint>
#include <math.h>

#define S_LEN 2048
#define DM    1024
#define NH    16
#define DH    64
#define BATCH 2
#define MROWS (BATCH * S_LEN)   // 4096
#define QKV_STRIDE ((size_t)MROWS * DM)

using f16 = __half;

// ================= helpers =================
__device__ __forceinline__ uint32_t smem_to_u32(const void* p) {
    uint32_t a;
    asm("{ .reg .u64 t; cvta.to.shared.u64 t, %1; cvt.u32.u64 %0, t; }" : "=r"(a) : "l"(p));
    return a;
}
__device__ __forceinline__ void cp_async16(uint32_t saddr, const void* gaddr) {
    asm volatile("cp.async.cg.shared.global [%0], [%1], 16;" :: "r"(saddr), "l"(gaddr));
}
__device__ __forceinline__ void ldsm_x4(uint32_t* r, uint32_t addr) {
    asm volatile("ldmatrix.sync.aligned.m8n8.x4.shared.b16 {%0,%1,%2,%3}, [%4];"
                 : "=r"(r[0]), "=r"(r[1]), "=r"(r[2]), "=r"(r[3]) : "r"(addr));
}
__device__ __forceinline__ void ldsm_x2(uint32_t* r, uint32_t addr) {
    asm volatile("ldmatrix.sync.aligned.m8n8.x2.shared.b16 {%0,%1}, [%2];"
                 : "=r"(r[0]), "=r"(r[1]) : "r"(addr));
}
__device__ __forceinline__ void ldsm_x2t(uint32_t* r, uint32_t addr) {
    asm volatile("ldmatrix.sync.aligned.m8n8.x2.trans.shared.b16 {%0,%1}, [%2];"
                 : "=r"(r[0]), "=r"(r[1]) : "r"(addr));
}
// D += A(16x16 f16, row) * B(16x8 f16, col), fp32 acc
__device__ __forceinline__ void mma16816(float* d, const uint32_t* a, const uint32_t* b) {
    asm volatile(
        "mma.sync.aligned.m16n8k16.row.col.f32.f16.f16.f32 "
        "{%0,%1,%2,%3}, {%4,%5,%6,%7}, {%8,%9}, {%0,%1,%2,%3};\n"
        : "+f"(d[0]), "+f"(d[1]), "+f"(d[2]), "+f"(d[3])
        : "r"(a[0]), "r"(a[1]), "r"(a[2]), "r"(a[3]), "r"(b[0]), "r"(b[1]));
}
__device__ __forceinline__ float ex2(float x) {
    float r;
    asm("ex2.approx.f32 %0, %1;" : "=f"(r) : "f"(x));
    return r;
}

// ---- scratch (device globals) ----
__device__ f16 g_QKV[3][BATCH * NH * S_LEN * DH];   // [B,H,S,Dh] x {Q,K,V} (Q pre-scaled by 0.125*log2e)
__device__ f16 g_x16[MROWS * DM];
__device__ f16 g_a16[MROWS * DM];
__device__ f16 g_wT[4][DM * DM];     // q,k,v,o  ([N,K] layout)
__device__ float g_proj[MROWS * DM];

// ============================================================
// fp32 -> fp16
// ============================================================
__global__ __launch_bounds__(256)
void cvt_x(const float* __restrict__ in, f16* __restrict__ out) {
    const int i = blockIdx.x * 256 + threadIdx.x;
    const float2 v = ((const float2*)in)[i];
    ((__half2*)out)[i] = __floats2half2_rn(v.x, v.y);
}

// all 4 weights [K=1024, N=1024] fp32 -> wT [N, K] fp16, smem transpose
__global__ __launch_bounds__(256)
void cvt_wT_all(const float* __restrict__ w0, const float* __restrict__ w1,
                const float* __restrict__ w2, const float* __restrict__ w3,
                f16* __restrict__ wT) {
    __shared__ float t[32][33];
    const float* ws[4] = { w0, w1, w2, w3 };
    const int z = blockIdx.z;
    const float* w = ws[z];
    const int bn = blockIdx.x * 32, bk = blockIdx.y * 32;
    const int tx = threadIdx.x, ty = threadIdx.y;   // block (32, 8)
#pragma unroll
    for (int i = 0; i < 32; i += 8)
        t[ty + i][tx] = w[(size_t)(bk + ty + i) * DM + bn + tx];
    __syncthreads();
    const size_t zoff = (size_t)z * DM * DM;
#pragma unroll
    for (int i = 0; i < 32; i += 8)
        wT[zoff + (size_t)(bn + ty + i) * DM + bk + tx] = __float2half(t[tx][ty + i]);
}

// ============================================================
// HMMA fp16 GEMM: C[4096,1024] = A @ B^T (B stored [N,K]).
// 128x128 tile, K-tile 32, 4 warps (2x2), warp 64x64.
// Each B fragment feeds 4 MMAs, each A fragment 8 (2x reuse vs R15).
// cp.async 3-stage pipeline, one __syncthreads per k-iter.
// MODE 0: fp32 C row-major.  MODE 1: f16 scatter to [B,H,S,Dh]
//         (z==0 pre-scales by 0.125*log2e for base-2 attention).
// ============================================================
template <int MODE>
__global__ __launch_bounds__(128, 2)
void mma_gemm(const f16* __restrict__ A, const f16* __restrict__ Ball,
              float* __restrict__ C, f16* __restrict__ C16B)
{
    extern __shared__ char smd[];
    const int tid = threadIdx.x;
    const int lane = tid & 31, wid = tid >> 5;
    const int wm = wid & 1, wn = wid >> 1;            // 2 x 2 warp grid, warp 64x64
    const int m0 = blockIdx.y * 128, n0 = blockIdx.x * 128;
    const int z = blockIdx.z;
    const uint32_t sb = smem_to_u32(smd);

    const f16* B = Ball + (size_t)z * DM * DM;
    const f16* srcs[2] = { A + (size_t)m0 * DM, B + (size_t)n0 * DM };

    auto prefetch = [&](int kt) {
        const uint32_t bb = sb + (kt % 3) * 20480;
        const int k0 = kt * 32;
#pragma unroll
        for (int t = 0; t < 2; t++) {
            const f16* s = srcs[t] + k0;
            const uint32_t tb = bb + t * 10240;
#pragma unroll
            for (int i = 0; i < 4; i++) {
                const int idx = i * 128 + tid;
                const int r = idx >> 2, c = idx & 3;
                cp_async16(tb + r * 80 + c * 16, s + (size_t)r * DM + c * 8);
            }
        }
        asm volatile("cp.async.commit_group;");
    };

    prefetch(0);
    prefetch(1);

    float acc[4][8][4];
#pragma unroll
    for (int mt = 0; mt < 4; mt++)
#pragma unroll
        for (int nt = 0; nt < 8; nt++)
#pragma unroll
            for (int e = 0; e < 4; e++) acc[mt][nt][e] = 0.f;

    const int KT = DM / 32;   // 32
    for (int kt = 0; kt < KT; kt++) {
        if (kt == KT - 1) asm volatile("cp.async.wait_group 0;" ::: "memory");
        else              asm volatile("cp.async.wait_group 1;" ::: "memory");
        __syncthreads();
        if (kt + 2 < KT) prefetch(kt + 2);
        const uint32_t bb = sb + (kt % 3) * 20480;
#pragma unroll
        for (int ks = 0; ks < 2; ks++) {
            const int kk = ks * 16;
            uint32_t ah[4][4];
            const uint32_t acol = (uint32_t)(kk + (lane >> 4) * 8) * 2;
#pragma unroll
            for (int mt = 0; mt < 4; mt++)
                ldsm_x4(ah[mt], bb + (uint32_t)(wm * 64 + mt * 16 + (lane & 15)) * 80 + acol);
#pragma unroll
            for (int nt = 0; nt < 8; nt++) {
                uint32_t bf[2];
                const uint32_t rb = bb + 10240
                    + (uint32_t)(wn * 64 + nt * 8 + (lane & 7)) * 80
                    + (uint32_t)(kk + ((lane >> 3) & 1) * 8) * 2;
                ldsm_x2(bf, rb);
#pragma unroll
                for (int mt = 0; mt < 4; mt++) mma16816(acc[mt][nt], ah[mt], bf);
            }
        }
    }

    f16* C16 = (MODE == 1) ? C16B + (size_t)z * QKV_STRIDE : nullptr;
    const float oscl = (MODE == 1 && z == 0) ? 0.125f * 1.44269504f : 1.0f;

#pragma unroll
    for (int mt = 0; mt < 4; mt++)
#pragma unroll
    for (int nt = 0; nt < 8; nt++) {
        const int r0 = m0 + wm * 64 + mt * 16 + (lane >> 2);
        const int c0 = n0 + wn * 64 + nt * 8 + (lane & 3) * 2;
#pragma unroll
        for (int e = 0; e < 4; e++) {
            const int r = r0 + (e >> 1) * 8;
            const int c = c0 + (e & 1);
            const float v = acc[mt][nt][e];
            if (MODE == 0) {
                C[(size_t)r * DM + c] = v;
            } else {
                const int b = r >> 11, s = r & 2047;
                const int h = c >> 6, d = c & 63;
                C16[(((size_t)(b * NH + h)) * S_LEN + s) * DH + d] = __float2half(v * oscl);
            }
        }
    }
}

// ============================================================
// FA2-style fp16 flash attention: BM=128, BN=64, Dh=64, 4 warps,
// each warp 32 query rows (2 m-tiles). Base-2 online softmax
// (Q pre-scaled by 0.125*log2e; raw ex2.approx).
// Row-sum computed BY THE PV MMA: the 16B V-row padding holds
// {1,0,...,0}, and nt=8 accumulates P @ ones under the same
// rescale recurrence as O -> no fp32 sum reduction, no rl state.
// Causal mask only on the last two (diagonal) kv-tiles.
// ============================================================
__global__ __launch_bounds__(128)
void attn_kernel() {
    extern __shared__ char smd[];
    const int tid = threadIdx.x, lane = tid & 31, wid = tid >> 5;   // 4 warps
    const int qt = (int)gridDim.x - 1 - (int)blockIdx.x;   // heavy tiles first
    const int bh = blockIdx.y;
    const int b = bh >> 4, h = bh & 15;
    const int q0 = qt * 128;
    const int groupID = lane >> 2, tid4 = lane & 3;
    const uint32_t sb = smem_to_u32(smd);
    const uint32_t KV0 = 18432, KVSZ = 18432;      // per buf: K(9216), V(9216); rows 144B
    const int nkt = 2 * qt + 2;

    const size_t base_off = (size_t)bh * S_LEN * DH;

    // Q load
    {
        const f16* q = g_QKV[0] + base_off + (size_t)q0 * DH;
#pragma unroll
        for (int i = 0; i < 8; i++) {
            const int idx = i * 128 + tid;
            const int r = idx >> 3, c = idx & 7;
            cp_async16(sb + r * 144 + c * 16, q + r * 64 + c * 8);
        }
    }
    // Fill V-row pads (cols 64..71) with {1,0,...,0} in BOTH buffers.
    // cp.async only ever writes bytes 0..127 of each row, so this persists.
    {
        const int buf = tid >> 6, row = tid & 63;
        *(uint4*)(smd + KV0 + buf * KVSZ + 9216 + row * 144 + 128) =
            make_uint4(0x3C00u, 0u, 0u, 0u);
    }
    auto kvload = [&](int kt) {
        const uint32_t bb = sb + KV0 + (kt & 1) * KVSZ;
        const size_t off = base_off + (size_t)kt * 64 * DH;
        const f16* srcs[2] = { g_QKV[1] + off, g_QKV[2] + off };
#pragma unroll
        for (int t = 0; t < 2; t++) {
            const uint32_t tb = bb + t * 9216;
            const f16* s = srcs[t];
#pragma unroll
            for (int i = 0; i < 4; i++) {
                const int idx = i * 128 + tid;
                const int r = idx >> 3, c = idx & 7;
                cp_async16(tb + r * 144 + c * 16, s + r * 64 + c * 8);
            }
        }
        asm volatile("cp.async.commit_group;");
    };
    kvload(0);
    kvload(1);
    asm volatile("cp.async.wait_group 1;" ::: "memory");
    __syncthreads();

    // Hoist Q fragments for both m-tiles
    uint32_t qf[2][4][4];
#pragma unroll
    for (int mt = 0; mt < 2; mt++) {
        const uint32_t ra = sb + (uint32_t)(wid * 32 + mt * 16 + (lane & 15)) * 144
                            + (uint32_t)((lane >> 4) * 8) * 2;
#pragma unroll
        for (int ks = 0; ks < 4; ks++) ldsm_x4(qf[mt][ks], ra + ks * 32);
    }

    float rm[2][2];
#pragma unroll
    for (int mt = 0; mt < 2; mt++) { rm[mt][0] = rm[mt][1] = -1e30f; }
    float oacc[2][9][4];   // nt=8 is the P@ones (row-sum) column
#pragma unroll
    for (int mt = 0; mt < 2; mt++)
#pragma unroll
        for (int nt = 0; nt < 9; nt++)
#pragma unroll
            for (int e = 0; e < 4; e++) oacc[mt][nt][e] = 0.f;

    for (int kt = 0; kt < nkt; kt++) {
        const uint32_t kb = sb + KV0 + (kt & 1) * KVSZ;
        const uint32_t vb = kb + 9216;

        // ---- S = Q @ K^T, 32x64 per warp ----
        float sacc[2][8][4];
#pragma unroll
        for (int mt = 0; mt < 2; mt++)
#pragma unroll
            for (int nt = 0; nt < 8; nt++)
#pragma unroll
                for (int e = 0; e < 4; e++) sacc[mt][nt][e] = 0.f;

#pragma unroll
        for (int ks = 0; ks < 4; ks++) {
#pragma unroll
            for (int nt = 0; nt < 8; nt++) {
                uint32_t kf[2];
                const uint32_t rb = kb + (uint32_t)(nt * 8 + (lane & 7)) * 144
                                    + (uint32_t)(ks * 16 + ((lane >> 3) & 1) * 8) * 2;
                ldsm_x2(kf, rb);
#pragma unroll
                for (int mt = 0; mt < 2; mt++) mma16816(sacc[mt][nt], qf[mt][ks], kf);
            }
        }

        // ---- causal mask only on diagonal-straddling tiles ----
        if (kt >= nkt - 2) {
#pragma unroll
            for (int mt = 0; mt < 2; mt++) {
                const int row0 = q0 + wid * 32 + mt * 16 + groupID;
#pragma unroll
                for (int nt = 0; nt < 8; nt++) {
                    const int c0 = kt * 64 + nt * 8 + tid4 * 2;
#pragma unroll
                    for (int e = 0; e < 4; e++) {
                        const int col = c0 + (e & 1);
                        const int row = row0 + ((e >> 1) << 3);
                        if (col > row) sacc[mt][nt][e] = -10000000.0f;
                    }
                }
            }
        }

        // ---- base-2 online softmax per m-tile (no sum reduction) ----
#pragma unroll
        for (int mt = 0; mt < 2; mt++) {
            float mx0 = rm[mt][0], mx1 = rm[mt][1];
#pragma unroll
            for (int nt = 0; nt < 8; nt++) {
                mx0 = fmaxf(mx0, fmaxf(sacc[mt][nt][0], sacc[mt][nt][1]));
                mx1 = fmaxf(mx1, fmaxf(sacc[mt][nt][2], sacc[mt][nt][3]));
            }
            mx0 = fmaxf(mx0, __shfl_xor_sync(0xffffffffu, mx0, 1));
            mx0 = fmaxf(mx0, __shfl_xor_sync(0xffffffffu, mx0, 2));
            mx1 = fmaxf(mx1, __shfl_xor_sync(0xffffffffu, mx1, 1));
            mx1 = fmaxf(mx1, __shfl_xor_sync(0xffffffffu, mx1, 2));
#pragma unroll
            for (int nt = 0; nt < 8; nt++) {
                sacc[mt][nt][0] = ex2(sacc[mt][nt][0] - mx0);
                sacc[mt][nt][1] = ex2(sacc[mt][nt][1] - mx0);
                sacc[mt][nt][2] = ex2(sacc[mt][nt][2] - mx1);
                sacc[mt][nt][3] = ex2(sacc[mt][nt][3] - mx1);
            }
            const float sc0 = ex2(rm[mt][0] - mx0), sc1 = ex2(rm[mt][1] - mx1);
            rm[mt][0] = mx0;  rm[mt][1] = mx1;
#pragma unroll
            for (int nt = 0; nt < 9; nt++) {
                oacc[mt][nt][0] *= sc0; oacc[mt][nt][1] *= sc0;
                oacc[mt][nt][2] *= sc1; oacc[mt][nt][3] *= sc1;
            }
        }

        // ---- O += P @ V (nt=8 = ones column -> row sums) ----
#pragma unroll
        for (int j = 0; j < 4; j++) {
            uint32_t pf[2][4];
#pragma unroll
            for (int mt = 0; mt < 2; mt++) {
                __half2 h0 = __floats2half2_rn(sacc[mt][2 * j][0],     sacc[mt][2 * j][1]);
                __half2 h1 = __floats2half2_rn(sacc[mt][2 * j][2],     sacc[mt][2 * j][3]);
                __half2 h2 = __floats2half2_rn(sacc[mt][2 * j + 1][0], sacc[mt][2 * j + 1][1]);
                __half2 h3 = __floats2half2_rn(sacc[mt][2 * j + 1][2], sacc[mt][2 * j + 1][3]);
                pf[mt][0] = *(uint32_t*)&h0;  pf[mt][1] = *(uint32_t*)&h1;
                pf[mt][2] = *(uint32_t*)&h2;  pf[mt][3] = *(uint32_t*)&h3;
            }
#pragma unroll
            for (int nt = 0; nt < 9; nt++) {
                uint32_t vf[2];
                const uint32_t rb = vb + (uint32_t)(j * 16 + (lane & 15)) * 144
                                    + (uint32_t)(nt * 8) * 2;
                ldsm_x2t(vf, rb);
#pragma unroll
                for (int mt = 0; mt < 2; mt++) mma16816(oacc[mt][nt], pf[mt], vf);
            }
        }

        // ---- pipeline next KV tile ----
        if (kt + 1 < nkt) {
            __syncthreads();
            if (kt + 2 < nkt) {
                kvload(kt + 2);
                asm volatile("cp.async.wait_group 1;" ::: "memory");
            } else {
                asm volatile("cp.async.wait_group 0;" ::: "memory");
            }
        }
    }

    // ---- epilogue: O / l  -> fp16 merged-head layout ----
    // l for row groupID is oacc[mt][8][0] of the quad leader (col 64);
    // l for row groupID+8 is oacc[mt][8][2] of the quad leader.
#pragma unroll
    for (int mt = 0; mt < 2; mt++) {
        const int qlead = lane & ~3;
        const float l0 = __shfl_sync(0xffffffffu, oacc[mt][8][0], qlead);
        const float l1 = __shfl_sync(0xffffffffu, oacc[mt][8][2], qlead);
        const float inv0 = 1.f / l0, inv1 = 1.f / l1;
        const size_t m0 = (size_t)b * S_LEN + q0 + wid * 32 + mt * 16 + groupID;
        const size_t m1 = m0 + 8;
#pragma unroll
        for (int nt = 0; nt < 8; nt++) {
            const int n = h * 64 + nt * 8 + tid4 * 2;
            *(__half2*)&g_a16[m0 * DM + n] =
                __floats2half2_rn(oacc[mt][nt][0] * inv0, oacc[mt][nt][1] * inv0);
            *(__half2*)&g_a16[m1 * DM + n] =
                __floats2half2_rn(oacc[mt][nt][2] * inv1, oacc[mt][nt][3] * inv1);
        }
    }
}

// ============================================================
// residual + LayerNorm (float4 vectorized)
// ============================================================
__global__ __launch_bounds__(256)
void ln_kernel(const float* __restrict__ P, const float* __restrict__ X,
               const float* __restrict__ gamma, const float* __restrict__ beta,
               float* __restrict__ out) {
    __shared__ float red[9];
    const int row = blockIdx.x;
    const int tid = threadIdx.x;
    const float4 pv = ((const float4*)(P + (size_t)row * DM))[tid];
    const float4 xv = ((const float4*)(X + (size_t)row * DM))[tid];

    float y[4] = { pv.x + xv.x, pv.y + xv.y, pv.z + xv.z, pv.w + xv.w };
    float sum = y[0] + y[1] + y[2] + y[3];
    for (int o = 16; o; o >>= 1) sum += __shfl_xor_sync(0xffffffffu, sum, o);
    const int w = tid >> 5, l = tid & 31;
    if (l == 0) red[w] = sum;
    __syncthreads();
    if (w == 0) {
        float t = (l < 8) ? red[l] : 0.f;
        for (int o = 4; o; o >>= 1) t += __shfl_xor_sync(0xffffffffu, t, o);
        if (l == 0) red[8] = t;
    }
    __syncthreads();
    const float mu = red[8] * (1.f / DM);
    __syncthreads();

    float vs = 0.f;
#pragma unroll
    for (int u = 0; u < 4; u++) { const float d = y[u] - mu; vs += d * d; }
    for (int o = 16; o; o >>= 1) vs += __shfl_xor_sync(0xffffffffu, vs, o);
    if (l == 0) red[w] = vs;
    __syncthreads();
    if (w == 0) {
        float t = (l < 8) ? red[l] : 0.f;
        for (int o = 4; o; o >>= 1) t += __shfl_xor_sync(0xffffffffu, t, o);
        if (l == 0) red[8] = t;
    }
    __syncthreads();
    const float var = red[8] * (1.f / DM);
    const float inv = rsqrtf(var + 1e-5f);

    const float4 gv = ((const float4*)gamma)[tid];
    const float4 bv = ((const float4*)beta)[tid];
    float4 ov;
    ov.x = (y[0] - mu) * inv * gv.x + bv.x;
    ov.y = (y[1] - mu) * inv * gv.y + bv.y;
    ov.z = (y[2] - mu) * inv * gv.z + bv.z;
    ov.w = (y[3] - mu) * inv * gv.w + bv.w;
    ((float4*)(out + (size_t)row * DM))[tid] = ov;
}

// ============================================================
extern "C" void kernel_launch(void* const* d_in, const int* in_sizes, int n_in,
                              void* d_out, int out_size) {
    const float* x     = (const float*)d_in[0];
    const float* wq    = (const float*)d_in[1];
    const float* wk    = (const float*)d_in[2];
    const float* wv    = (const float*)d_in[3];
    const float* wo    = (const float*)d_in[4];
    const float* gamma = (const float*)d_in[5];
    const float* beta  = (const float*)d_in[6];
    float* out = (float*)d_out;

    void *pQKV, *px16, *pa16, *pwT, *pP;
    cudaGetSymbolAddress(&pQKV, g_QKV);
    cudaGetSymbolAddress(&px16, g_x16);
    cudaGetSymbolAddress(&pa16, g_a16);
    cudaGetSymbolAddress(&pwT, g_wT);
    cudaGetSymbolAddress(&pP, g_proj);

    f16* x16 = (f16*)px16;
    f16* a16 = (f16*)pa16;
    f16* wT  = (f16*)pwT;

    // conversions
    cvt_x<<<(MROWS * DM / 2) / 256, 256>>>(x, x16);
    cvt_wT_all<<<dim3(32, 32, 4), dim3(32, 8)>>>(wq, wk, wv, wo, wT);

    const int gemm_smem = 3 * 20480;   // 60 KB (3-stage)
    cudaFuncSetAttribute(mma_gemm<0>, cudaFuncAttributeMaxDynamicSharedMemorySize, gemm_smem);
    cudaFuncSetAttribute(mma_gemm<1>, cudaFuncAttributeMaxDynamicSharedMemorySize, gemm_smem);

    // fused QKV projections: grid.z = weight/output slot (z=0 Q pre-scaled by 0.125*log2e)
    mma_gemm<1><<<dim3(DM / 128, MROWS / 128, 3), 128, gemm_smem>>>(
        x16, wT, nullptr, (f16*)pQKV);

    const int attn_smem = 55296;       // Q (18432) + 2 KV bufs (36864)
    cudaFuncSetAttribute(attn_kernel, cudaFuncAttributeMaxDynamicSharedMemorySize, attn_smem);
    attn_kernel<<<dim3(S_LEN / 128, BATCH * NH), 128, attn_smem>>>();

    // output projection (weight slot 3)
    mma_gemm<0><<<dim3(DM / 128, MROWS / 128, 1), 128, gemm_smem>>>(
        a16, wT + 3 * (size_t)DM * DM, (float*)pP, nullptr);

    ln_kernel<<<MROWS, 256>>>((const float*)pP, x, gamma, beta, out);
}

// round 17
// speedup vs baseline: 2.4812x; 1.0201x over previous
#include <cuda_runtime.h>
#include <cuda_fp16.h>
#include <cstdint>
#include <math.h>

#define S_LEN 2048
#define DM    1024
#define NH    16
#define DH    64
#define BATCH 2
#define MROWS (BATCH * S_LEN)   // 4096
#define QKV_STRIDE ((size_t)MROWS * DM)

using f16 = __half;

// ================= helpers =================
__device__ __forceinline__ uint32_t smem_to_u32(const void* p) {
    uint32_t a;
    asm("{ .reg .u64 t; cvta.to.shared.u64 t, %1; cvt.u32.u64 %0, t; }" : "=r"(a) : "l"(p));
    return a;
}
__device__ __forceinline__ void cp_async16(uint32_t saddr, const void* gaddr) {
    asm volatile("cp.async.cg.shared.global [%0], [%1], 16;" :: "r"(saddr), "l"(gaddr));
}
__device__ __forceinline__ void ldsm_x4(uint32_t* r, uint32_t addr) {
    asm volatile("ldmatrix.sync.aligned.m8n8.x4.shared.b16 {%0,%1,%2,%3}, [%4];"
                 : "=r"(r[0]), "=r"(r[1]), "=r"(r[2]), "=r"(r[3]) : "r"(addr));
}
__device__ __forceinline__ void ldsm_x2t(uint32_t* r, uint32_t addr) {
    asm volatile("ldmatrix.sync.aligned.m8n8.x2.trans.shared.b16 {%0,%1}, [%2];"
                 : "=r"(r[0]), "=r"(r[1]) : "r"(addr));
}
__device__ __forceinline__ void ldsm_x4t(uint32_t* r, uint32_t addr) {
    asm volatile("ldmatrix.sync.aligned.m8n8.x4.trans.shared.b16 {%0,%1,%2,%3}, [%4];"
                 : "=r"(r[0]), "=r"(r[1]), "=r"(r[2]), "=r"(r[3]) : "r"(addr));
}
// D += A(16x16 f16, row) * B(16x8 f16, col), fp32 acc
__device__ __forceinline__ void mma16816(float* d, const uint32_t* a, const uint32_t* b) {
    asm volatile(
        "mma.sync.aligned.m16n8k16.row.col.f32.f16.f16.f32 "
        "{%0,%1,%2,%3}, {%4,%5,%6,%7}, {%8,%9}, {%0,%1,%2,%3};\n"
        : "+f"(d[0]), "+f"(d[1]), "+f"(d[2]), "+f"(d[3])
        : "r"(a[0]), "r"(a[1]), "r"(a[2]), "r"(a[3]), "r"(b[0]), "r"(b[1]));
}
__device__ __forceinline__ float ex2(float x) {
    float r;
    asm("ex2.approx.f32 %0, %1;" : "=f"(r) : "f"(x));
    return r;
}
// packed half2 2^x
__device__ __forceinline__ uint32_t ex2_h2(float a, float b) {
    __half2 h = __floats2half2_rn(a, b);
    uint32_t hi = *(uint32_t*)&h, ro;
    asm("ex2.approx.f16x2 %0, %1;" : "=r"(ro) : "r"(hi));
    return ro;
}

// ---- scratch (device globals) ----
__device__ f16 g_QKV[3][BATCH * NH * S_LEN * DH];   // [B,H,S,Dh] x {Q,K,V} (Q pre-scaled by 0.125*log2e)
__device__ f16 g_x16[MROWS * DM];
__device__ f16 g_a16[MROWS * DM];
__device__ f16 g_wT[4][DM * DM];     // q,k,v,o  ([N,K] layout)
__device__ float g_proj[MROWS * DM];

// ============================================================
// fp32 -> fp16
// ============================================================
__global__ __launch_bounds__(256)
void cvt_x(const float* __restrict__ in, f16* __restrict__ out) {
    const int i = blockIdx.x * 256 + threadIdx.x;
    const float2 v = ((const float2*)in)[i];
    ((__half2*)out)[i] = __floats2half2_rn(v.x, v.y);
}

// all 4 weights [K=1024, N=1024] fp32 -> wT [N, K] fp16, smem transpose
__global__ __launch_bounds__(256)
void cvt_wT_all(const float* __restrict__ w0, const float* __restrict__ w1,
                const float* __restrict__ w2, const float* __restrict__ w3,
                f16* __restrict__ wT) {
    __shared__ float t[32][33];
    const float* ws[4] = { w0, w1, w2, w3 };
    const int z = blockIdx.z;
    const float* w = ws[z];
    const int bn = blockIdx.x * 32, bk = blockIdx.y * 32;
    const int tx = threadIdx.x, ty = threadIdx.y;   // block (32, 8)
#pragma unroll
    for (int i = 0; i < 32; i += 8)
        t[ty + i][tx] = w[(size_t)(bk + ty + i) * DM + bn + tx];
    __syncthreads();
    const size_t zoff = (size_t)z * DM * DM;
#pragma unroll
    for (int i = 0; i < 32; i += 8)
        wT[zoff + (size_t)(bn + ty + i) * DM + bk + tx] = __float2half(t[tx][ty + i]);
}

// ============================================================
// HMMA fp16 GEMM: C[4096,1024] = A @ B^T (B stored [N,K]).
// 128x128 tile, K-tile 32, 4 warps (2x2), warp 64x64.
// B fragments loaded pairwise with ldmatrix.x4.
// cp.async 3-stage pipeline, one __syncthreads per k-iter.
// MODE 0: fp32 C row-major.  MODE 1: f16 scatter to [B,H,S,Dh]
//         (z==0 pre-scales by 0.125*log2e for base-2 attention).
// ============================================================
template <int MODE>
__global__ __launch_bounds__(128, 2)
void mma_gemm(const f16* __restrict__ A, const f16* __restrict__ Ball,
              float* __restrict__ C, f16* __restrict__ C16B)
{
    extern __shared__ char smd[];
    const int tid = threadIdx.x;
    const int lane = tid & 31, wid = tid >> 5;
    const int wm = wid & 1, wn = wid >> 1;            // 2 x 2 warp grid, warp 64x64
    const int m0 = blockIdx.y * 128, n0 = blockIdx.x * 128;
    const int z = blockIdx.z;
    const uint32_t sb = smem_to_u32(smd);

    const f16* B = Ball + (size_t)z * DM * DM;
    const f16* srcs[2] = { A + (size_t)m0 * DM, B + (size_t)n0 * DM };

    auto prefetch = [&](int kt) {
        const uint32_t bb = sb + (kt % 3) * 20480;
        const int k0 = kt * 32;
#pragma unroll
        for (int t = 0; t < 2; t++) {
            const f16* s = srcs[t] + k0;
            const uint32_t tb = bb + t * 10240;
#pragma unroll
            for (int i = 0; i < 4; i++) {
                const int idx = i * 128 + tid;
                const int r = idx >> 2, c = idx & 3;
                cp_async16(tb + r * 80 + c * 16, s + (size_t)r * DM + c * 8);
            }
        }
        asm volatile("cp.async.commit_group;");
    };

    prefetch(0);
    prefetch(1);

    float acc[4][8][4];
#pragma unroll
    for (int mt = 0; mt < 4; mt++)
#pragma unroll
        for (int nt = 0; nt < 8; nt++)
#pragma unroll
            for (int e = 0; e < 4; e++) acc[mt][nt][e] = 0.f;

    const int KT = DM / 32;   // 32
    for (int kt = 0; kt < KT; kt++) {
        if (kt == KT - 1) asm volatile("cp.async.wait_group 0;" ::: "memory");
        else              asm volatile("cp.async.wait_group 1;" ::: "memory");
        __syncthreads();
        if (kt + 2 < KT) prefetch(kt + 2);
        const uint32_t bb = sb + (kt % 3) * 20480;
#pragma unroll
        for (int ks = 0; ks < 2; ks++) {
            const int kk = ks * 16;
            uint32_t ah[4][4];
            const uint32_t acol = (uint32_t)(kk + (lane >> 4) * 8) * 2;
#pragma unroll
            for (int mt = 0; mt < 4; mt++)
                ldsm_x4(ah[mt], bb + (uint32_t)(wm * 64 + mt * 16 + (lane & 15)) * 80 + acol);
#pragma unroll
            for (int np = 0; np < 4; np++) {   // n-tile pairs (2np, 2np+1)
                uint32_t bf[4];
                const uint32_t rb = bb + 10240
                    + (uint32_t)(wn * 64 + np * 16 + ((lane >> 4) << 3) + (lane & 7)) * 80
                    + (uint32_t)(kk + ((lane >> 3) & 1) * 8) * 2;
                ldsm_x4(bf, rb);
#pragma unroll
                for (int mt = 0; mt < 4; mt++) {
                    mma16816(acc[mt][2 * np],     ah[mt], bf);
                    mma16816(acc[mt][2 * np + 1], ah[mt], bf + 2);
                }
            }
        }
    }

    f16* C16 = (MODE == 1) ? C16B + (size_t)z * QKV_STRIDE : nullptr;
    const float oscl = (MODE == 1 && z == 0) ? 0.125f * 1.44269504f : 1.0f;

#pragma unroll
    for (int mt = 0; mt < 4; mt++)
#pragma unroll
    for (int nt = 0; nt < 8; nt++) {
        const int r0 = m0 + wm * 64 + mt * 16 + (lane >> 2);
        const int c0 = n0 + wn * 64 + nt * 8 + (lane & 3) * 2;
#pragma unroll
        for (int e = 0; e < 4; e++) {
            const int r = r0 + (e >> 1) * 8;
            const int c = c0 + (e & 1);
            const float v = acc[mt][nt][e];
            if (MODE == 0) {
                C[(size_t)r * DM + c] = v;
            } else {
                const int b = r >> 11, s = r & 2047;
                const int h = c >> 6, d = c & 63;
                C16[(((size_t)(b * NH + h)) * S_LEN + s) * DH + d] = __float2half(v * oscl);
            }
        }
    }
}

// ============================================================
// FA2-style fp16 flash attention: BM=128, BN=64, Dh=64, 4 warps,
// each warp 32 query rows (2 m-tiles). Base-2 online softmax with
// fp16x2 MUFU exponentials (P is fp16 for the MMA anyway).
// Row-sum via the PV MMA ones-column (V pad = {1,0,...}).
// K loaded with ldmatrix.x4 (n-tile pairs), V with x4.trans.
// Causal mask only on the last two (diagonal) kv-tiles.
// ============================================================
__global__ __launch_bounds__(128)
void attn_kernel() {
    extern __shared__ char smd[];
    const int tid = threadIdx.x, lane = tid & 31, wid = tid >> 5;   // 4 warps
    const int qt = (int)gridDim.x - 1 - (int)blockIdx.x;   // heavy tiles first
    const int bh = blockIdx.y;
    const int b = bh >> 4, h = bh & 15;
    const int q0 = qt * 128;
    const int groupID = lane >> 2, tid4 = lane & 3;
    const uint32_t sb = smem_to_u32(smd);
    const uint32_t KV0 = 18432, KVSZ = 18432;      // per buf: K(9216), V(9216); rows 144B
    const int nkt = 2 * qt + 2;

    const size_t base_off = (size_t)bh * S_LEN * DH;

    // Q load
    {
        const f16* q = g_QKV[0] + base_off + (size_t)q0 * DH;
#pragma unroll
        for (int i = 0; i < 8; i++) {
            const int idx = i * 128 + tid;
            const int r = idx >> 3, c = idx & 7;
            cp_async16(sb + r * 144 + c * 16, q + r * 64 + c * 8);
        }
    }
    // Fill V-row pads (cols 64..71) with {1,0,...,0} in BOTH buffers.
    {
        const int buf = tid >> 6, row = tid & 63;
        *(uint4*)(smd + KV0 + buf * KVSZ + 9216 + row * 144 + 128) =
            make_uint4(0x3C00u, 0u, 0u, 0u);
    }
    auto kvload = [&](int kt) {
        const uint32_t bb = sb + KV0 + (kt & 1) * KVSZ;
        const size_t off = base_off + (size_t)kt * 64 * DH;
        const f16* srcs[2] = { g_QKV[1] + off, g_QKV[2] + off };
#pragma unroll
        for (int t = 0; t < 2; t++) {
            const uint32_t tb = bb + t * 9216;
            const f16* s = srcs[t];
#pragma unroll
            for (int i = 0; i < 4; i++) {
                const int idx = i * 128 + tid;
                const int r = idx >> 3, c = idx & 7;
                cp_async16(tb + r * 144 + c * 16, s + r * 64 + c * 8);
            }
        }
        asm volatile("cp.async.commit_group;");
    };
    kvload(0);
    kvload(1);
    asm volatile("cp.async.wait_group 1;" ::: "memory");
    __syncthreads();

    // Hoist Q fragments for both m-tiles
    uint32_t qf[2][4][4];
#pragma unroll
    for (int mt = 0; mt < 2; mt++) {
        const uint32_t ra = sb + (uint32_t)(wid * 32 + mt * 16 + (lane & 15)) * 144
                            + (uint32_t)((lane >> 4) * 8) * 2;
#pragma unroll
        for (int ks = 0; ks < 4; ks++) ldsm_x4(qf[mt][ks], ra + ks * 32);
    }

    float rm[2][2];
#pragma unroll
    for (int mt = 0; mt < 2; mt++) { rm[mt][0] = rm[mt][1] = -1e30f; }
    float oacc[2][9][4];   // nt=8 is the P@ones (row-sum) column
#pragma unroll
    for (int mt = 0; mt < 2; mt++)
#pragma unroll
        for (int nt = 0; nt < 9; nt++)
#pragma unroll
            for (int e = 0; e < 4; e++) oacc[mt][nt][e] = 0.f;

    for (int kt = 0; kt < nkt; kt++) {
        const uint32_t kb = sb + KV0 + (kt & 1) * KVSZ;
        const uint32_t vb = kb + 9216;

        // ---- S = Q @ K^T, 32x64 per warp; K frags via ldmatrix.x4 ----
        float sacc[2][8][4];
#pragma unroll
        for (int mt = 0; mt < 2; mt++)
#pragma unroll
            for (int nt = 0; nt < 8; nt++)
#pragma unroll
                for (int e = 0; e < 4; e++) sacc[mt][nt][e] = 0.f;

#pragma unroll
        for (int ks = 0; ks < 4; ks++) {
#pragma unroll
            for (int np = 0; np < 4; np++) {   // n-tile pairs
                uint32_t kf[4];
                const uint32_t rb = kb
                    + (uint32_t)(np * 16 + ((lane >> 4) << 3) + (lane & 7)) * 144
                    + (uint32_t)(ks * 16 + ((lane >> 3) & 1) * 8) * 2;
                ldsm_x4(kf, rb);
#pragma unroll
                for (int mt = 0; mt < 2; mt++) {
                    mma16816(sacc[mt][2 * np],     qf[mt][ks], kf);
                    mma16816(sacc[mt][2 * np + 1], qf[mt][ks], kf + 2);
                }
            }
        }

        // ---- causal mask only on diagonal-straddling tiles ----
        if (kt >= nkt - 2) {
#pragma unroll
            for (int mt = 0; mt < 2; mt++) {
                const int row0 = q0 + wid * 32 + mt * 16 + groupID;
#pragma unroll
                for (int nt = 0; nt < 8; nt++) {
                    const int c0 = kt * 64 + nt * 8 + tid4 * 2;
#pragma unroll
                    for (int e = 0; e < 4; e++) {
                        const int col = c0 + (e & 1);
                        const int row = row0 + ((e >> 1) << 3);
                        if (col > row) sacc[mt][nt][e] = -10000000.0f;
                    }
                }
            }
        }

        // ---- base-2 online softmax; exp in fp16x2, result IS the P frag ----
        uint32_t pp[2][8][2];   // pp[mt][nt][0]=(e0,e1) rows g, pp[..][1]=(e2,e3) rows g+8
#pragma unroll
        for (int mt = 0; mt < 2; mt++) {
            float mx0 = rm[mt][0], mx1 = rm[mt][1];
#pragma unroll
            for (int nt = 0; nt < 8; nt++) {
                mx0 = fmaxf(mx0, fmaxf(sacc[mt][nt][0], sacc[mt][nt][1]));
                mx1 = fmaxf(mx1, fmaxf(sacc[mt][nt][2], sacc[mt][nt][3]));
            }
            mx0 = fmaxf(mx0, __shfl_xor_sync(0xffffffffu, mx0, 1));
            mx0 = fmaxf(mx0, __shfl_xor_sync(0xffffffffu, mx0, 2));
            mx1 = fmaxf(mx1, __shfl_xor_sync(0xffffffffu, mx1, 1));
            mx1 = fmaxf(mx1, __shfl_xor_sync(0xffffffffu, mx1, 2));
#pragma unroll
            for (int nt = 0; nt < 8; nt++) {
                pp[mt][nt][0] = ex2_h2(sacc[mt][nt][0] - mx0, sacc[mt][nt][1] - mx0);
                pp[mt][nt][1] = ex2_h2(sacc[mt][nt][2] - mx1, sacc[mt][nt][3] - mx1);
            }
            const float sc0 = ex2(rm[mt][0] - mx0), sc1 = ex2(rm[mt][1] - mx1);
            rm[mt][0] = mx0;  rm[mt][1] = mx1;
#pragma unroll
            for (int nt = 0; nt < 9; nt++) {
                oacc[mt][nt][0] *= sc0; oacc[mt][nt][1] *= sc0;
                oacc[mt][nt][2] *= sc1; oacc[mt][nt][3] *= sc1;
            }
        }

        // ---- O += P @ V (nt=8 = ones column); V frags via ldmatrix.x4.trans ----
#pragma unroll
        for (int j = 0; j < 4; j++) {
            uint32_t pf[2][4];
#pragma unroll
            for (int mt = 0; mt < 2; mt++) {
                pf[mt][0] = pp[mt][2 * j][0];
                pf[mt][1] = pp[mt][2 * j][1];
                pf[mt][2] = pp[mt][2 * j + 1][0];
                pf[mt][3] = pp[mt][2 * j + 1][1];
            }
#pragma unroll
            for (int np = 0; np < 4; np++) {   // n-tile pairs 0..7
                uint32_t vf[4];
                const uint32_t rb = vb + (uint32_t)(j * 16 + (lane & 15)) * 144
                                    + (uint32_t)(np * 16 + ((lane >> 4) & 1) * 8) * 2;
                ldsm_x4t(vf, rb);
#pragma unroll
                for (int mt = 0; mt < 2; mt++) {
                    mma16816(oacc[mt][2 * np],     pf[mt], vf);
                    mma16816(oacc[mt][2 * np + 1], pf[mt], vf + 2);
                }
            }
            {   // ones column (nt=8)
                uint32_t vf[2];
                const uint32_t rb = vb + (uint32_t)(j * 16 + (lane & 15)) * 144 + 128;
                ldsm_x2t(vf, rb);
#pragma unroll
                for (int mt = 0; mt < 2; mt++) mma16816(oacc[mt][8], pf[mt], vf);
            }
        }

        // ---- pipeline next KV tile ----
        if (kt + 1 < nkt) {
            __syncthreads();
            if (kt + 2 < nkt) {
                kvload(kt + 2);
                asm volatile("cp.async.wait_group 1;" ::: "memory");
            } else {
                asm volatile("cp.async.wait_group 0;" ::: "memory");
            }
        }
    }

    // ---- epilogue: O / l  -> fp16 merged-head layout ----
#pragma unroll
    for (int mt = 0; mt < 2; mt++) {
        const int qlead = lane & ~3;
        const float l0 = __shfl_sync(0xffffffffu, oacc[mt][8][0], qlead);
        const float l1 = __shfl_sync(0xffffffffu, oacc[mt][8][2], qlead);
        const float inv0 = 1.f / l0, inv1 = 1.f / l1;
        const size_t m0 = (size_t)b * S_LEN + q0 + wid * 32 + mt * 16 + groupID;
        const size_t m1 = m0 + 8;
#pragma unroll
        for (int nt = 0; nt < 8; nt++) {
            const int n = h * 64 + nt * 8 + tid4 * 2;
            *(__half2*)&g_a16[m0 * DM + n] =
                __floats2half2_rn(oacc[mt][nt][0] * inv0, oacc[mt][nt][1] * inv0);
            *(__half2*)&g_a16[m1 * DM + n] =
                __floats2half2_rn(oacc[mt][nt][2] * inv1, oacc[mt][nt][3] * inv1);
        }
    }
}

// ============================================================
// residual + LayerNorm (float4 vectorized)
// ============================================================
__global__ __launch_bounds__(256)
void ln_kernel(const float* __restrict__ P, const float* __restrict__ X,
               const float* __restrict__ gamma, const float* __restrict__ beta,
               float* __restrict__ out) {
    __shared__ float red[9];
    const int row = blockIdx.x;
    const int tid = threadIdx.x;
    const float4 pv = ((const float4*)(P + (size_t)row * DM))[tid];
    const float4 xv = ((const float4*)(X + (size_t)row * DM))[tid];

    float y[4] = { pv.x + xv.x, pv.y + xv.y, pv.z + xv.z, pv.w + xv.w };
    float sum = y[0] + y[1] + y[2] + y[3];
    for (int o = 16; o; o >>= 1) sum += __shfl_xor_sync(0xffffffffu, sum, o);
    const int w = tid >> 5, l = tid & 31;
    if (l == 0) red[w] = sum;
    __syncthreads();
    if (w == 0) {
        float t = (l < 8) ? red[l] : 0.f;
        for (int o = 4; o; o >>= 1) t += __shfl_xor_sync(0xffffffffu, t, o);
        if (l == 0) red[8] = t;
    }
    __syncthreads();
    const float mu = red[8] * (1.f / DM);
    __syncthreads();

    float vs = 0.f;
#pragma unroll
    for (int u = 0; u < 4; u++) { const float d = y[u] - mu; vs += d * d; }
    for (int o = 16; o; o >>= 1) vs += __shfl_xor_sync(0xffffffffu, vs, o);
    if (l == 0) red[w] = vs;
    __syncthreads();
    if (w == 0) {
        float t = (l < 8) ? red[l] : 0.f;
        for (int o = 4; o; o >>= 1) t += __shfl_xor_sync(0xffffffffu, t, o);
        if (l == 0) red[8] = t;
    }
    __syncthreads();
    const float var = red[8] * (1.f / DM);
    const float inv = rsqrtf(var + 1e-5f);

    const float4 gv = ((const float4*)gamma)[tid];
    const float4 bv = ((const float4*)beta)[tid];
    float4 ov;
    ov.x = (y[0] - mu) * inv * gv.x + bv.x;
    ov.y = (y[1] - mu) * inv * gv.y + bv.y;
    ov.z = (y[2] - mu) * inv * gv.z + bv.z;
    ov.w = (y[3] - mu) * inv * gv.w + bv.w;
    ((float4*)(out + (size_t)row * DM))[tid] = ov;
}

// ============================================================
extern "C" void kernel_launch(void* const* d_in, const int* in_sizes, int n_in,
                              void* d_out, int out_size) {
    const float* x     = (const float*)d_in[0];
    const float* wq    = (const float*)d_in[1];
    const float* wk    = (const float*)d_in[2];
    const float* wv    = (const float*)d_in[3];
    const float* wo    = (const float*)d_in[4];
    const float* gamma = (const float*)d_in[5];
    const float* beta  = (const float*)d_in[6];
    float* out = (float*)d_out;

    void *pQKV, *px16, *pa16, *pwT, *pP;
    cudaGetSymbolAddress(&pQKV, g_QKV);
    cudaGetSymbolAddress(&px16, g_x16);
    cudaGetSymbolAddress(&pa16, g_a16);
    cudaGetSymbolAddress(&pwT, g_wT);
    cudaGetSymbolAddress(&pP, g_proj);

    f16* x16 = (f16*)px16;
    f16* a16 = (f16*)pa16;
    f16* wT  = (f16*)pwT;

    // conversions
    cvt_x<<<(MROWS * DM / 2) / 256, 256>>>(x, x16);
    cvt_wT_all<<<dim3(32, 32, 4), dim3(32, 8)>>>(wq, wk, wv, wo, wT);

    const int gemm_smem = 3 * 20480;   // 60 KB (3-stage)
    cudaFuncSetAttribute(mma_gemm<0>, cudaFuncAttributeMaxDynamicSharedMemorySize, gemm_smem);
    cudaFuncSetAttribute(mma_gemm<1>, cudaFuncAttributeMaxDynamicSharedMemorySize, gemm_smem);

    // fused QKV projections: grid.z = weight/output slot (z=0 Q pre-scaled by 0.125*log2e)
    mma_gemm<1><<<dim3(DM / 128, MROWS / 128, 3), 128, gemm_smem>>>(
        x16, wT, nullptr, (f16*)pQKV);

    const int attn_smem = 55296;       // Q (18432) + 2 KV bufs (36864)
    cudaFuncSetAttribute(attn_kernel, cudaFuncAttributeMaxDynamicSharedMemorySize, attn_smem);
    attn_kernel<<<dim3(S_LEN / 128, BATCH * NH), 128, attn_smem>>>();

    // output projection (weight slot 3)
    mma_gemm<0><<<dim3(DM / 128, MROWS / 128, 1), 128, gemm_smem>>>(
        a16, wT + 3 * (size_t)DM * DM, (float*)pP, nullptr);

    ln_kernel<<<MROWS, 256>>>((const float*)pP, x, gamma, beta, out);
}